// round 12
// baseline (speedup 1.0000x reference)
#include <cuda_runtime.h>
#include <cuda_bf16.h>
#include <cuda_fp16.h>
#include <cstdint>
#include <math.h>

#define NNODES 50000
#define NEDGES 400000
#define NGRAPHS 64
#define FDIM 512      // HEADS * GAT_DIM
#define CDIM 128      // GAT_DIM
#define NEG_SLOPE 0.2f

// ---------------- device scratch (static, no allocation) ----------------
__device__ __half g_xlh[NNODES * FDIM];   // 50 MB (L2-resident gather target)
__device__ __half g_xrh[NNODES * FDIM];   // 50 MB
__device__ float g_h[NNODES * CDIM];      // 25.6 MB
__device__ __nv_bfloat16 g_ah[NNODES * 256];   // hi (cols 0-127) | lo (cols 128-255)
__device__ __nv_bfloat16 g_wbig[4][384 * 512]; // split weights: Wl1,Wr1,Wl2,Wr2
__device__ int   g_deg[NNODES];
__device__ int   g_rowptr[NNODES + 1];
__device__ int   g_cur[NNODES];
__device__ int   g_srcs[NEDGES];
__device__ int   g_bsum[64];
__device__ float g_psum[NGRAPHS * CDIM];
__device__ float g_pcnt[NGRAPHS];

__device__ __forceinline__ float lrelu(float v) {
    return fmaxf(v, 0.0f) + NEG_SLOPE * fminf(v, 0.0f);
}
__device__ __forceinline__ float elu(float v) {
    return v > 0.0f ? v : expm1f(v);
}

// ---------------- CSR build ----------------
__global__ void k_zero_all() {
    int t = blockIdx.x * blockDim.x + threadIdx.x;
    if (t < NNODES) g_deg[t] = 0;
    if (t < NGRAPHS * CDIM) g_psum[t] = 0.0f;
    if (t < NGRAPHS) g_pcnt[t] = 0.0f;
}

__global__ void k_hist(const int* __restrict__ ei, int E) {
    int e = blockIdx.x * blockDim.x + threadIdx.x;
    if (e < E) atomicAdd(&g_deg[ei[E + e]], 1);
}

__global__ void k_scan1() {
    __shared__ int sh[1024];
    int i = blockIdx.x * 1024 + threadIdx.x;
    int v = (i < NNODES) ? g_deg[i] : 0;
    sh[threadIdx.x] = v;
    __syncthreads();
    for (int off = 1; off < 1024; off <<= 1) {
        int t = (threadIdx.x >= off) ? sh[threadIdx.x - off] : 0;
        __syncthreads();
        sh[threadIdx.x] += t;
        __syncthreads();
    }
    if (i < NNODES) g_rowptr[i] = sh[threadIdx.x] - v;
    if (threadIdx.x == 1023) g_bsum[blockIdx.x] = sh[1023];
}

// fused block-offset + apply
__global__ void k_scan3() {
    __shared__ int soff;
    int blk = blockIdx.x;
    if (threadIdx.x < 32) {
        int v = 0;
        if (threadIdx.x < blk) v = g_bsum[threadIdx.x];
        if (threadIdx.x + 32 < blk) v += g_bsum[threadIdx.x + 32];
#pragma unroll
        for (int o = 16; o; o >>= 1) v += __shfl_xor_sync(0xffffffffu, v, o);
        if (threadIdx.x == 0) {
            soff = v;
            if (blk == (int)gridDim.x - 1) g_rowptr[NNODES] = v + g_bsum[blk];
        }
    }
    __syncthreads();
    int i = blk * 1024 + threadIdx.x;
    if (i < NNODES) {
        int v = g_rowptr[i] + soff;
        g_rowptr[i] = v;
        g_cur[i] = v;
    }
}

__global__ void k_scatter(const int* __restrict__ ei, int E) {
    int e = blockIdx.x * blockDim.x + threadIdx.x;
    if (e < E) {
        int d = ei[E + e];
        int pos = atomicAdd(&g_cur[d], 1);
        g_srcs[pos] = ei[e];
    }
}

// ---------------- layer 0 transform (d_in = 3, memory bound) ----------------
__global__ void k_lin0(const float* __restrict__ x,
                       const float* __restrict__ Wl, const float* __restrict__ bl,
                       const float* __restrict__ Wr, const float* __restrict__ br) {
    int t = blockIdx.x * blockDim.x + threadIdx.x;
    int n = t >> 7;
    if (n >= NNODES) return;
    int j = (t & 127) * 4;
    float x0 = x[n * 3 + 0], x1 = x[n * 3 + 1], x2 = x[n * 3 + 2];

    float4 w0 = *(const float4*)(Wl + 0 * FDIM + j);
    float4 w1 = *(const float4*)(Wl + 1 * FDIM + j);
    float4 w2 = *(const float4*)(Wl + 2 * FDIM + j);
    float4 bb = *(const float4*)(bl + j);
    float4 o;
    o.x = bb.x + x0 * w0.x + x1 * w1.x + x2 * w2.x;
    o.y = bb.y + x0 * w0.y + x1 * w1.y + x2 * w2.y;
    o.z = bb.z + x0 * w0.z + x1 * w1.z + x2 * w2.z;
    o.w = bb.w + x0 * w0.w + x1 * w1.w + x2 * w2.w;
    {
        union { __half2 h[2]; uint2 u; } pk;
        pk.h[0] = __floats2half2_rn(o.x, o.y);
        pk.h[1] = __floats2half2_rn(o.z, o.w);
        *(uint2*)(g_xlh + (size_t)n * FDIM + j) = pk.u;
    }

    w0 = *(const float4*)(Wr + 0 * FDIM + j);
    w1 = *(const float4*)(Wr + 1 * FDIM + j);
    w2 = *(const float4*)(Wr + 2 * FDIM + j);
    bb = *(const float4*)(br + j);
    o.x = bb.x + x0 * w0.x + x1 * w1.x + x2 * w2.x;
    o.y = bb.y + x0 * w0.y + x1 * w1.y + x2 * w2.y;
    o.z = bb.z + x0 * w0.z + x1 * w1.z + x2 * w2.z;
    o.w = bb.w + x0 * w0.w + x1 * w1.w + x2 * w2.w;
    {
        union { __half2 h[2]; uint2 u; } pk;
        pk.h[0] = __floats2half2_rn(o.x, o.y);
        pk.h[1] = __floats2half2_rn(o.z, o.w);
        *(uint2*)(g_xrh + (size_t)n * FDIM + j) = pk.u;
    }
}

// ---------------- weight split prep: W[128,512] fp32 -> [384,512] bf16 ----------------
__global__ void k_wprep(const float* __restrict__ Wl1, const float* __restrict__ Wr1,
                        const float* __restrict__ Wl2, const float* __restrict__ Wr2) {
    int idx = blockIdx.x * 256 + threadIdx.x;
    if (idx >= 384 * 512) return;
    int r = idx >> 9, n = idx & 511;
    int sr = (r < 128) ? r : ((r < 256) ? r - 128 : r - 256);
    bool want_lo = (r >= 128 && r < 256);
    const float* Ws[4] = {Wl1, Wr1, Wl2, Wr2};
#pragma unroll
    for (int w = 0; w < 4; w++) {
        float v = Ws[w][sr * 512 + n];
        __nv_bfloat16 h = __float2bfloat16(v);
        g_wbig[w][idx] = want_lo ? __float2bfloat16(v - __bfloat162float(h)) : h;
    }
}

// ---------------- tensor-core GEMM ----------------
#define GM_AST 40
#define GM_BST 136
#define AS_STAGE_B (128 * GM_AST * 2)   // 10240 B
#define BS_STAGE_B (32 * GM_BST * 2)    // 8704 B
#define SMEM_GEMM (4 * AS_STAGE_B + 3 * BS_STAGE_B)   // 67072 B

__device__ __forceinline__ void ldsm_x4(uint32_t r[4], uint32_t addr) {
    asm volatile("ldmatrix.sync.aligned.m8n8.x4.shared.b16 {%0,%1,%2,%3}, [%4];"
                 : "=r"(r[0]), "=r"(r[1]), "=r"(r[2]), "=r"(r[3]) : "r"(addr));
}
__device__ __forceinline__ void ldsm_x4_t(uint32_t r[4], uint32_t addr) {
    asm volatile("ldmatrix.sync.aligned.m8n8.x4.trans.shared.b16 {%0,%1,%2,%3}, [%4];"
                 : "=r"(r[0]), "=r"(r[1]), "=r"(r[2]), "=r"(r[3]) : "r"(addr));
}
__device__ __forceinline__ void mma16816(float c[4], const uint32_t a[4],
                                         uint32_t b0, uint32_t b1) {
    asm volatile(
        "mma.sync.aligned.m16n8k16.row.col.f32.bf16.bf16.f32 "
        "{%0,%1,%2,%3}, {%4,%5,%6,%7}, {%8,%9}, {%0,%1,%2,%3};"
        : "+f"(c[0]), "+f"(c[1]), "+f"(c[2]), "+f"(c[3])
        : "r"(a[0]), "r"(a[1]), "r"(a[2]), "r"(a[3]), "r"(b0), "r"(b1));
}
__device__ __forceinline__ void cp16(uint32_t dst, const void* src, int sz) {
    asm volatile("cp.async.cg.shared.global [%0], [%1], 16, %2;"
                 :: "r"(dst), "l"(src), "r"(sz));
}

__global__ void __launch_bounds__(256) k_gemm_mma(int lbase,
                                                  const float* __restrict__ bl,
                                                  const float* __restrict__ br) {
    extern __shared__ __align__(16) char dynsm[];
    uint32_t as_base = (uint32_t)__cvta_generic_to_shared(dynsm);
    uint32_t bs_base = as_base + 4 * AS_STAGE_B;

    const __nv_bfloat16* wbig = g_wbig[lbase + blockIdx.z];
    const float* bias = blockIdx.z ? br : bl;
    __half* Cout = blockIdx.z ? g_xrh : g_xlh;

    int tid = threadIdx.x;
    int m0 = blockIdx.x * 128, n0 = blockIdx.y * 128;
    int warp = tid >> 5, lane = tid & 31;
    int wm = warp >> 1, wn = warp & 1;

    int ar[2], aq[2], brw[2], bq[2];
    int aok[2];
#pragma unroll
    for (int it = 0; it < 2; it++) {
        int s = tid + it * 256;
        ar[it] = s >> 2;  aq[it] = s & 3;
        brw[it] = s >> 4; bq[it] = s & 15;
        aok[it] = (m0 + ar[it]) < NNODES ? 16 : 0;
    }

    float c[2][8][4];
#pragma unroll
    for (int f = 0; f < 2; f++)
#pragma unroll
        for (int j = 0; j < 8; j++)
#pragma unroll
            for (int q = 0; q < 4; q++) c[f][j][q] = 0.0f;

    uint32_t a_ld[2][2], b_ld[4][2];
#pragma unroll
    for (int f = 0; f < 2; f++)
#pragma unroll
        for (int kh = 0; kh < 2; kh++)
            a_ld[f][kh] = as_base +
                ((wm * 32 + f * 16 + (lane & 15)) * GM_AST + kh * 16 + (lane >> 4) * 8) * 2;
#pragma unroll
    for (int g = 0; g < 4; g++)
#pragma unroll
        for (int kh = 0; kh < 2; kh++)
            b_ld[g][kh] = bs_base +
                ((kh * 16 + (lane & 15)) * GM_BST + wn * 64 + g * 16 + (lane >> 4) * 8) * 2;

    auto load_chunk = [&](int kt) {
        int aslot = kt & 3;
        int bslot = kt % 3;
        bool loadA = (kt < 4) || (kt >= 8);
        int acol = (kt < 8) ? (kt & 3) * 32 : ((kt - 8) * 32 + 128);
#pragma unroll
        for (int it = 0; it < 2; it++) {
            if (loadA)
                cp16(as_base + aslot * AS_STAGE_B + (ar[it] * GM_AST + aq[it] * 8) * 2,
                     g_ah + (size_t)(m0 + ar[it]) * 256 + acol + aq[it] * 8, aok[it]);
            cp16(bs_base + bslot * BS_STAGE_B + (brw[it] * GM_BST + bq[it] * 8) * 2,
                 wbig + (size_t)(kt * 32 + brw[it]) * 512 + n0 + bq[it] * 8, 16);
        }
    };

#pragma unroll
    for (int p = 0; p < 2; p++) {
        load_chunk(p);
        asm volatile("cp.async.commit_group;");
    }

    for (int kt = 0; kt < 12; kt++) {
        asm volatile("cp.async.wait_group 1;");
        __syncthreads();
        int soffA = (kt & 3) * AS_STAGE_B;
        int soffB = (kt % 3) * BS_STAGE_B;

        uint32_t a[2][2][4];
#pragma unroll
        for (int f = 0; f < 2; f++)
#pragma unroll
            for (int kh = 0; kh < 2; kh++)
                ldsm_x4(a[f][kh], a_ld[f][kh] + soffA);

        if (kt + 2 < 12) load_chunk(kt + 2);
        asm volatile("cp.async.commit_group;");

#pragma unroll
        for (int g = 0; g < 4; g++) {
            uint32_t b0[4], b1[4];
            ldsm_x4_t(b0, b_ld[g][0] + soffB);
            ldsm_x4_t(b1, b_ld[g][1] + soffB);
#pragma unroll
            for (int f = 0; f < 2; f++) {
                mma16816(c[f][2 * g],     a[f][0], b0[0], b0[1]);
                mma16816(c[f][2 * g + 1], a[f][0], b0[2], b0[3]);
                mma16816(c[f][2 * g],     a[f][1], b1[0], b1[1]);
                mma16816(c[f][2 * g + 1], a[f][1], b1[2], b1[3]);
            }
        }
    }

    // epilogue -> fp16
    int r0 = lane >> 2, cp = (lane & 3) * 2;
#pragma unroll
    for (int f = 0; f < 2; f++) {
        int gr = m0 + wm * 32 + f * 16 + r0;
#pragma unroll
        for (int j = 0; j < 8; j++) {
            int col = n0 + wn * 64 + j * 8 + cp;
            float b0v = bias[col], b1v = bias[col + 1];
            if (gr < NNODES) {
                __half2 o = __floats2half2_rn(c[f][j][0] + b0v, c[f][j][1] + b1v);
                *(__half2*)&Cout[(size_t)gr * FDIM + col] = o;
            }
            if (gr + 8 < NNODES) {
                __half2 o = __floats2half2_rn(c[f][j][2] + b0v, c[f][j][3] + b1v);
                *(__half2*)&Cout[(size_t)(gr + 8) * FDIM + col] = o;
            }
        }
    }
}

// ---------------- fused edge pass: direct-exp segment softmax ----------------
// FOUR warps per destination node (one head each). Block = 256 = 8 warps = 2 nodes.
// Lane l owns channels 4l..4l+3 of the warp's head. 5-shuffle full-butterfly
// reduction: every lane ends with e, computes exp locally (no broadcast).
// Depth-3 gather prefetch covers L2 latency.
__global__ void __launch_bounds__(256) k_edge(const float* __restrict__ att,
                                              const float* __restrict__ bias) {
    __shared__ float att_s[FDIM];
    __shared__ float part[2][4][CDIM];   // [node][head][channel]
    int tid = threadIdx.x;
    for (int i = tid; i < FDIM; i += 256) att_s[i] = att[i];
    __syncthreads();

    int warp = tid >> 5, lane = tid & 31;
    int nodeLocal = warp >> 2;          // 0..1
    int h = warp & 3;                   // head index
    int gw = blockIdx.x * 2 + nodeLocal;   // NNODES = 25000*2 exactly
    const size_t hoff = (size_t)h * 128 + lane * 4;

    // xr channels for this warp's head
    float4 xrv;
    {
        float2 raw = *(const float2*)(g_xrh + (size_t)gw * FDIM + hoff);
        __half2 h01 = *(__half2*)&raw.x;
        __half2 h23 = *(__half2*)&raw.y;
        float2 f01 = __half22float2(h01), f23 = __half22float2(h23);
        xrv = make_float4(f01.x, f01.y, f23.x, f23.y);
    }
    float4 attv = *reinterpret_cast<const float4*>(&att_s[h * 128 + lane * 4]);

    float den = 0.f;
    float a0 = 0.f, a1 = 0.f, a2 = 0.f, a3 = 0.f;

    int s0 = g_rowptr[gw], s1 = g_rowptr[gw + 1];

    // depth-3 prefetch ring
    float2 b0v, b1v, b2v;
    if (s0 < s1)     b0v = *(const float2*)(g_xlh + (size_t)g_srcs[s0] * FDIM + hoff);
    if (s0 + 1 < s1) b1v = *(const float2*)(g_xlh + (size_t)g_srcs[s0 + 1] * FDIM + hoff);
    if (s0 + 2 < s1) b2v = *(const float2*)(g_xlh + (size_t)g_srcs[s0 + 2] * FDIM + hoff);

    for (int k = s0; k < s1; k++) {
        float2 cur = b0v;
        b0v = b1v; b1v = b2v;
        if (k + 3 < s1)
            b2v = *(const float2*)(g_xlh + (size_t)g_srcs[k + 3] * FDIM + hoff);

        __half2 h01 = *(__half2*)&cur.x;
        __half2 h23 = *(__half2*)&cur.y;
        float2 f01 = __half22float2(h01), f23 = __half22float2(h23);
        float xl0 = f01.x, xl1 = f01.y, xl2 = f23.x, xl3 = f23.y;

        float p = attv.x * lrelu(xl0 + xrv.x)
                + attv.y * lrelu(xl1 + xrv.y)
                + attv.z * lrelu(xl2 + xrv.z)
                + attv.w * lrelu(xl3 + xrv.w);
        p += __shfl_xor_sync(0xffffffffu, p, 16);
        p += __shfl_xor_sync(0xffffffffu, p, 8);
        p += __shfl_xor_sync(0xffffffffu, p, 4);
        p += __shfl_xor_sync(0xffffffffu, p, 2);
        p += __shfl_xor_sync(0xffffffffu, p, 1);
        float pw = __expf(fminf(p, 60.f));

        den += pw;
        a0 = fmaf(pw, xl0, a0);
        a1 = fmaf(pw, xl1, a1);
        a2 = fmaf(pw, xl2, a2);
        a3 = fmaf(pw, xl3, a3);
    }

    // quarter head-mean contribution for this head
    float inv = (den > 0.f) ? 0.25f / den : 0.f;
    a0 *= inv; a1 *= inv; a2 *= inv; a3 *= inv;

    if (h != 0) {
        part[nodeLocal][h][lane * 4 + 0] = a0;
        part[nodeLocal][h][lane * 4 + 1] = a1;
        part[nodeLocal][h][lane * 4 + 2] = a2;
        part[nodeLocal][h][lane * 4 + 3] = a3;
    }
    __syncthreads();
    if (h == 0) {
#pragma unroll
        for (int j = 1; j < 4; j++) {
            a0 += part[nodeLocal][j][lane * 4 + 0];
            a1 += part[nodeLocal][j][lane * 4 + 1];
            a2 += part[nodeLocal][j][lane * 4 + 2];
            a3 += part[nodeLocal][j][lane * 4 + 3];
        }

        float4 bv = *reinterpret_cast<const float4*>(&bias[lane * 4]);
        float4 out;
        out.x = elu(a0 + bv.x);
        out.y = elu(a1 + bv.y);
        out.z = elu(a2 + bv.z);
        out.w = elu(a3 + bv.w);
        *reinterpret_cast<float4*>(&g_h[(size_t)gw * CDIM + lane * 4]) = out;

        // bf16 hi/lo split for the next layer's tensor-core GEMM
        __nv_bfloat16 h0 = __float2bfloat16(out.x), h1 = __float2bfloat16(out.y);
        __nv_bfloat16 h2 = __float2bfloat16(out.z), h3 = __float2bfloat16(out.w);
        __nv_bfloat16 l0 = __float2bfloat16(out.x - __bfloat162float(h0));
        __nv_bfloat16 l1 = __float2bfloat16(out.y - __bfloat162float(h1));
        __nv_bfloat16 l2 = __float2bfloat16(out.z - __bfloat162float(h2));
        __nv_bfloat16 l3 = __float2bfloat16(out.w - __bfloat162float(h3));
        __nv_bfloat162 hpk[2] = {{h0, h1}, {h2, h3}};
        __nv_bfloat162 lpk[2] = {{l0, l1}, {l2, l3}};
        *reinterpret_cast<float2*>(&g_ah[(size_t)gw * 256 + lane * 4])       = *reinterpret_cast<float2*>(hpk);
        *reinterpret_cast<float2*>(&g_ah[(size_t)gw * 256 + 128 + lane * 4]) = *reinterpret_cast<float2*>(lpk);
    }
}

// ---------------- global mean pool (sum + count fused) + final linear ----------------
__global__ void k_pool_acc(const int* __restrict__ batch) {
    int c = threadIdx.x;           // 128 threads
    int n0 = blockIdx.x * 64;
    int n1 = min(n0 + 64, NNODES);
    if (n0 >= NNODES) return;
    float local = 0.f;
    int cnt = 0;
    int curg = batch[n0];
    for (int n = n0; n < n1; n++) {
        int g = batch[n];
        if (g != curg) {
            atomicAdd(&g_psum[curg * CDIM + c], local);
            if (c == 0) atomicAdd(&g_pcnt[curg], (float)cnt);
            local = 0.f; cnt = 0;
            curg = g;
        }
        local += g_h[(size_t)n * CDIM + c];
        cnt++;
    }
    atomicAdd(&g_psum[curg * CDIM + c], local);
    if (c == 0) atomicAdd(&g_pcnt[curg], (float)cnt);
}

__global__ void k_final(const float* __restrict__ W, const float* __restrict__ b,
                        float* __restrict__ out) {
    __shared__ float gsh[CDIM];
    int g = blockIdx.x;
    int j = threadIdx.x;
    float inv = 1.0f / fmaxf(g_pcnt[g], 1.0f);
    gsh[j] = g_psum[g * CDIM + j] * inv;
    __syncthreads();
    float acc = b[j];
    for (int k = 0; k < CDIM; k++) acc = fmaf(gsh[k], W[k * CDIM + j], acc);
    out[g * CDIM + j] = acc;
}

// ---------------- launcher ----------------
extern "C" void kernel_launch(void* const* d_in, const int* in_sizes, int n_in,
                              void* d_out, int out_size) {
    const float* x     = (const float*)d_in[0];
    const int*   ei    = (const int*)d_in[1];   // [2, E] int32
    const int*   batch = (const int*)d_in[2];

    const float* Wl[3] = {(const float*)d_in[3],  (const float*)d_in[9],  (const float*)d_in[15]};
    const float* bl[3] = {(const float*)d_in[4],  (const float*)d_in[10], (const float*)d_in[16]};
    const float* Wr[3] = {(const float*)d_in[5],  (const float*)d_in[11], (const float*)d_in[17]};
    const float* br[3] = {(const float*)d_in[6],  (const float*)d_in[12], (const float*)d_in[18]};
    const float* at[3] = {(const float*)d_in[7],  (const float*)d_in[13], (const float*)d_in[19]};
    const float* bb[3] = {(const float*)d_in[8],  (const float*)d_in[14], (const float*)d_in[20]};
    const float* linW  = (const float*)d_in[21];
    const float* linb  = (const float*)d_in[22];
    float* out = (float*)d_out;

    int E = in_sizes[1] / 2;
    int nb = (NNODES + 1023) / 1024;

    cudaFuncSetAttribute(k_gemm_mma, cudaFuncAttributeMaxDynamicSharedMemorySize, SMEM_GEMM);

    // CSR build (per replay; deterministic work)
    k_zero_all<<<(NNODES + 255) / 256, 256>>>();
    k_hist<<<(E + 255) / 256, 256>>>(ei, E);
    k_scan1<<<nb, 1024>>>();
    k_scan3<<<nb, 1024>>>();
    k_scatter<<<(E + 255) / 256, 256>>>(ei, E);

    // weight split prep (cheap)
    k_wprep<<<(384 * 512 + 255) / 256, 256>>>(Wl[1], Wr[1], Wl[2], Wr[2]);

    // layer 0
    k_lin0<<<(NNODES * 128 + 255) / 256, 256>>>(x, Wl[0], bl[0], Wr[0], br[0]);
    k_edge<<<NNODES / 2, 256>>>(at[0], bb[0]);

    // layers 1, 2: tensor-core split-bf16 GEMM then fused edge pass
    dim3 gg((NNODES + 127) / 128, 4, 2);
    k_gemm_mma<<<gg, 256, SMEM_GEMM>>>(0, bl[1], br[1]);
    k_edge<<<NNODES / 2, 256>>>(at[1], bb[1]);
    k_gemm_mma<<<gg, 256, SMEM_GEMM>>>(2, bl[2], br[2]);
    k_edge<<<NNODES / 2, 256>>>(at[2], bb[2]);

    // pool + final linear
    k_pool_acc<<<(NNODES + 63) / 64, 128>>>(batch);
    k_final<<<NGRAPHS, CDIM>>>(linW, linb, out);
}

// round 13
// speedup vs baseline: 1.0867x; 1.0867x over previous
#include <cuda_runtime.h>
#include <cuda_bf16.h>
#include <cuda_fp16.h>
#include <cstdint>
#include <math.h>

#define NNODES 50000
#define NEDGES 400000
#define NGRAPHS 64
#define FDIM 512      // HEADS * GAT_DIM
#define CDIM 128      // GAT_DIM
#define NEG_SLOPE 0.2f

// Permuted activation layout for g_xlh/g_xrh rows (512 halfs):
//   pos(h, c) = (h>>1)*256 + (c>>2)*8 + (h&1)*4 + (c&3)
// so warp hp (heads 2hp, 2hp+1), lane l reads ONE float4 at hp*256 + l*8:
//   halfs[0..3] = head 2hp   channels 4l..4l+3
//   halfs[4..7] = head 2hp+1 channels 4l..4l+3

// ---------------- device scratch (static, no allocation) ----------------
__device__ __half g_xlh[NNODES * FDIM];   // 50 MB (permuted layout)
__device__ __half g_xrh[NNODES * FDIM];   // 50 MB (permuted layout)
__device__ float g_h[NNODES * CDIM];      // 25.6 MB
__device__ __nv_bfloat16 g_ah[NNODES * 256];   // hi (cols 0-127) | lo (cols 128-255)
__device__ __nv_bfloat16 g_wbig[4][384 * 512]; // split weights: Wl1,Wr1,Wl2,Wr2
__device__ int   g_deg[NNODES];
__device__ int   g_rowptr[NNODES + 1];
__device__ int   g_cur[NNODES];
__device__ int   g_srcs[NEDGES];
__device__ int   g_bsum[64];
__device__ float g_psum[NGRAPHS * CDIM];
__device__ float g_pcnt[NGRAPHS];

__device__ __forceinline__ float lrelu(float v) {
    return fmaxf(v, 0.0f) + NEG_SLOPE * fminf(v, 0.0f);
}
__device__ __forceinline__ float elu(float v) {
    return v > 0.0f ? v : expm1f(v);
}
__device__ __forceinline__ int permpos(int col) {   // standard col -> permuted pos
    int h = col >> 7, c = col & 127;
    return ((h >> 1) << 8) + ((c >> 2) << 3) + ((h & 1) << 2) + (c & 3);
}

// ---------------- CSR build ----------------
__global__ void k_zero_all() {
    int t = blockIdx.x * blockDim.x + threadIdx.x;
    if (t < NNODES) g_deg[t] = 0;
    if (t < NGRAPHS * CDIM) g_psum[t] = 0.0f;
    if (t < NGRAPHS) g_pcnt[t] = 0.0f;
}

__global__ void k_hist(const int* __restrict__ ei, int E) {
    int e = blockIdx.x * blockDim.x + threadIdx.x;
    if (e < E) atomicAdd(&g_deg[ei[E + e]], 1);
}

__global__ void k_scan1() {
    __shared__ int sh[1024];
    int i = blockIdx.x * 1024 + threadIdx.x;
    int v = (i < NNODES) ? g_deg[i] : 0;
    sh[threadIdx.x] = v;
    __syncthreads();
    for (int off = 1; off < 1024; off <<= 1) {
        int t = (threadIdx.x >= off) ? sh[threadIdx.x - off] : 0;
        __syncthreads();
        sh[threadIdx.x] += t;
        __syncthreads();
    }
    if (i < NNODES) g_rowptr[i] = sh[threadIdx.x] - v;
    if (threadIdx.x == 1023) g_bsum[blockIdx.x] = sh[1023];
}

// fused block-offset + apply
__global__ void k_scan3() {
    __shared__ int soff;
    int blk = blockIdx.x;
    if (threadIdx.x < 32) {
        int v = 0;
        if (threadIdx.x < blk) v = g_bsum[threadIdx.x];
        if (threadIdx.x + 32 < blk) v += g_bsum[threadIdx.x + 32];
#pragma unroll
        for (int o = 16; o; o >>= 1) v += __shfl_xor_sync(0xffffffffu, v, o);
        if (threadIdx.x == 0) {
            soff = v;
            if (blk == (int)gridDim.x - 1) g_rowptr[NNODES] = v + g_bsum[blk];
        }
    }
    __syncthreads();
    int i = blk * 1024 + threadIdx.x;
    if (i < NNODES) {
        int v = g_rowptr[i] + soff;
        g_rowptr[i] = v;
        g_cur[i] = v;
    }
}

__global__ void k_scatter(const int* __restrict__ ei, int E) {
    int e = blockIdx.x * blockDim.x + threadIdx.x;
    if (e < E) {
        int d = ei[E + e];
        int pos = atomicAdd(&g_cur[d], 1);
        g_srcs[pos] = ei[e];
    }
}

// ---------------- layer 0 transform (d_in = 3, memory bound) ----------------
__global__ void k_lin0(const float* __restrict__ x,
                       const float* __restrict__ Wl, const float* __restrict__ bl,
                       const float* __restrict__ Wr, const float* __restrict__ br) {
    int t = blockIdx.x * blockDim.x + threadIdx.x;
    int n = t >> 7;
    if (n >= NNODES) return;
    int j = (t & 127) * 4;       // standard col base (4-aligned, single head)
    int pos = permpos(j);        // permuted write position (r=0, 4 contiguous halfs)
    float x0 = x[n * 3 + 0], x1 = x[n * 3 + 1], x2 = x[n * 3 + 2];

    float4 w0 = *(const float4*)(Wl + 0 * FDIM + j);
    float4 w1 = *(const float4*)(Wl + 1 * FDIM + j);
    float4 w2 = *(const float4*)(Wl + 2 * FDIM + j);
    float4 bb = *(const float4*)(bl + j);
    float4 o;
    o.x = bb.x + x0 * w0.x + x1 * w1.x + x2 * w2.x;
    o.y = bb.y + x0 * w0.y + x1 * w1.y + x2 * w2.y;
    o.z = bb.z + x0 * w0.z + x1 * w1.z + x2 * w2.z;
    o.w = bb.w + x0 * w0.w + x1 * w1.w + x2 * w2.w;
    {
        union { __half2 h[2]; uint2 u; } pk;
        pk.h[0] = __floats2half2_rn(o.x, o.y);
        pk.h[1] = __floats2half2_rn(o.z, o.w);
        *(uint2*)(g_xlh + (size_t)n * FDIM + pos) = pk.u;
    }

    w0 = *(const float4*)(Wr + 0 * FDIM + j);
    w1 = *(const float4*)(Wr + 1 * FDIM + j);
    w2 = *(const float4*)(Wr + 2 * FDIM + j);
    bb = *(const float4*)(br + j);
    o.x = bb.x + x0 * w0.x + x1 * w1.x + x2 * w2.x;
    o.y = bb.y + x0 * w0.y + x1 * w1.y + x2 * w2.y;
    o.z = bb.z + x0 * w0.z + x1 * w1.z + x2 * w2.z;
    o.w = bb.w + x0 * w0.w + x1 * w1.w + x2 * w2.w;
    {
        union { __half2 h[2]; uint2 u; } pk;
        pk.h[0] = __floats2half2_rn(o.x, o.y);
        pk.h[1] = __floats2half2_rn(o.z, o.w);
        *(uint2*)(g_xrh + (size_t)n * FDIM + pos) = pk.u;
    }
}

// ---------------- weight split prep: W[128,512] fp32 -> [384,512] bf16 ----------------
__global__ void k_wprep(const float* __restrict__ Wl1, const float* __restrict__ Wr1,
                        const float* __restrict__ Wl2, const float* __restrict__ Wr2) {
    int idx = blockIdx.x * 256 + threadIdx.x;
    if (idx >= 384 * 512) return;
    int r = idx >> 9, n = idx & 511;
    int sr = (r < 128) ? r : ((r < 256) ? r - 128 : r - 256);
    bool want_lo = (r >= 128 && r < 256);
    const float* Ws[4] = {Wl1, Wr1, Wl2, Wr2};
#pragma unroll
    for (int w = 0; w < 4; w++) {
        float v = Ws[w][sr * 512 + n];
        __nv_bfloat16 h = __float2bfloat16(v);
        g_wbig[w][idx] = want_lo ? __float2bfloat16(v - __bfloat162float(h)) : h;
    }
}

// ---------------- tensor-core GEMM ----------------
#define GM_AST 40
#define GM_BST 136
#define AS_STAGE_B (128 * GM_AST * 2)   // 10240 B
#define BS_STAGE_B (32 * GM_BST * 2)    // 8704 B
#define SMEM_GEMM (4 * AS_STAGE_B + 3 * BS_STAGE_B)   // 67072 B

__device__ __forceinline__ void ldsm_x4(uint32_t r[4], uint32_t addr) {
    asm volatile("ldmatrix.sync.aligned.m8n8.x4.shared.b16 {%0,%1,%2,%3}, [%4];"
                 : "=r"(r[0]), "=r"(r[1]), "=r"(r[2]), "=r"(r[3]) : "r"(addr));
}
__device__ __forceinline__ void ldsm_x4_t(uint32_t r[4], uint32_t addr) {
    asm volatile("ldmatrix.sync.aligned.m8n8.x4.trans.shared.b16 {%0,%1,%2,%3}, [%4];"
                 : "=r"(r[0]), "=r"(r[1]), "=r"(r[2]), "=r"(r[3]) : "r"(addr));
}
__device__ __forceinline__ void mma16816(float c[4], const uint32_t a[4],
                                         uint32_t b0, uint32_t b1) {
    asm volatile(
        "mma.sync.aligned.m16n8k16.row.col.f32.bf16.bf16.f32 "
        "{%0,%1,%2,%3}, {%4,%5,%6,%7}, {%8,%9}, {%0,%1,%2,%3};"
        : "+f"(c[0]), "+f"(c[1]), "+f"(c[2]), "+f"(c[3])
        : "r"(a[0]), "r"(a[1]), "r"(a[2]), "r"(a[3]), "r"(b0), "r"(b1));
}
__device__ __forceinline__ void cp16(uint32_t dst, const void* src, int sz) {
    asm volatile("cp.async.cg.shared.global [%0], [%1], 16, %2;"
                 :: "r"(dst), "l"(src), "r"(sz));
}

__global__ void __launch_bounds__(256) k_gemm_mma(int lbase,
                                                  const float* __restrict__ bl,
                                                  const float* __restrict__ br) {
    extern __shared__ __align__(16) char dynsm[];
    uint32_t as_base = (uint32_t)__cvta_generic_to_shared(dynsm);
    uint32_t bs_base = as_base + 4 * AS_STAGE_B;

    const __nv_bfloat16* wbig = g_wbig[lbase + blockIdx.z];
    const float* bias = blockIdx.z ? br : bl;
    __half* Cout = blockIdx.z ? g_xrh : g_xlh;

    int tid = threadIdx.x;
    int m0 = blockIdx.x * 128, n0 = blockIdx.y * 128;
    int warp = tid >> 5, lane = tid & 31;
    int wm = warp >> 1, wn = warp & 1;

    int ar[2], aq[2], brw[2], bq[2];
    int aok[2];
#pragma unroll
    for (int it = 0; it < 2; it++) {
        int s = tid + it * 256;
        ar[it] = s >> 2;  aq[it] = s & 3;
        brw[it] = s >> 4; bq[it] = s & 15;
        aok[it] = (m0 + ar[it]) < NNODES ? 16 : 0;
    }

    float c[2][8][4];
#pragma unroll
    for (int f = 0; f < 2; f++)
#pragma unroll
        for (int j = 0; j < 8; j++)
#pragma unroll
            for (int q = 0; q < 4; q++) c[f][j][q] = 0.0f;

    uint32_t a_ld[2][2], b_ld[4][2];
#pragma unroll
    for (int f = 0; f < 2; f++)
#pragma unroll
        for (int kh = 0; kh < 2; kh++)
            a_ld[f][kh] = as_base +
                ((wm * 32 + f * 16 + (lane & 15)) * GM_AST + kh * 16 + (lane >> 4) * 8) * 2;
#pragma unroll
    for (int g = 0; g < 4; g++)
#pragma unroll
        for (int kh = 0; kh < 2; kh++)
            b_ld[g][kh] = bs_base +
                ((kh * 16 + (lane & 15)) * GM_BST + wn * 64 + g * 16 + (lane >> 4) * 8) * 2;

    auto load_chunk = [&](int kt) {
        int aslot = kt & 3;
        int bslot = kt % 3;
        bool loadA = (kt < 4) || (kt >= 8);
        int acol = (kt < 8) ? (kt & 3) * 32 : ((kt - 8) * 32 + 128);
#pragma unroll
        for (int it = 0; it < 2; it++) {
            if (loadA)
                cp16(as_base + aslot * AS_STAGE_B + (ar[it] * GM_AST + aq[it] * 8) * 2,
                     g_ah + (size_t)(m0 + ar[it]) * 256 + acol + aq[it] * 8, aok[it]);
            cp16(bs_base + bslot * BS_STAGE_B + (brw[it] * GM_BST + bq[it] * 8) * 2,
                 wbig + (size_t)(kt * 32 + brw[it]) * 512 + n0 + bq[it] * 8, 16);
        }
    };

#pragma unroll
    for (int p = 0; p < 2; p++) {
        load_chunk(p);
        asm volatile("cp.async.commit_group;");
    }

    for (int kt = 0; kt < 12; kt++) {
        asm volatile("cp.async.wait_group 1;");
        __syncthreads();
        int soffA = (kt & 3) * AS_STAGE_B;
        int soffB = (kt % 3) * BS_STAGE_B;

        uint32_t a[2][2][4];
#pragma unroll
        for (int f = 0; f < 2; f++)
#pragma unroll
            for (int kh = 0; kh < 2; kh++)
                ldsm_x4(a[f][kh], a_ld[f][kh] + soffA);

        if (kt + 2 < 12) load_chunk(kt + 2);
        asm volatile("cp.async.commit_group;");

#pragma unroll
        for (int g = 0; g < 4; g++) {
            uint32_t b0[4], b1[4];
            ldsm_x4_t(b0, b_ld[g][0] + soffB);
            ldsm_x4_t(b1, b_ld[g][1] + soffB);
#pragma unroll
            for (int f = 0; f < 2; f++) {
                mma16816(c[f][2 * g],     a[f][0], b0[0], b0[1]);
                mma16816(c[f][2 * g + 1], a[f][0], b0[2], b0[3]);
                mma16816(c[f][2 * g],     a[f][1], b1[0], b1[1]);
                mma16816(c[f][2 * g + 1], a[f][1], b1[2], b1[3]);
            }
        }
    }

    // epilogue -> fp16 at permuted positions
    int r0 = lane >> 2, cp = (lane & 3) * 2;
#pragma unroll
    for (int f = 0; f < 2; f++) {
        int gr = m0 + wm * 32 + f * 16 + r0;
#pragma unroll
        for (int j = 0; j < 8; j++) {
            int col = n0 + wn * 64 + j * 8 + cp;   // standard col (even, pair col/col+1)
            int pos = permpos(col);                 // permuted pos (pair pos/pos+1)
            float b0v = bias[col], b1v = bias[col + 1];
            if (gr < NNODES) {
                __half2 o = __floats2half2_rn(c[f][j][0] + b0v, c[f][j][1] + b1v);
                *(__half2*)&Cout[(size_t)gr * FDIM + pos] = o;
            }
            if (gr + 8 < NNODES) {
                __half2 o = __floats2half2_rn(c[f][j][2] + b0v, c[f][j][3] + b1v);
                *(__half2*)&Cout[(size_t)(gr + 8) * FDIM + pos] = o;
            }
        }
    }
}

// ---------------- fused edge pass: direct-exp segment softmax ----------------
// TWO warps per destination node (head pair each). Block = 256 = 8 warps = 4 nodes.
// Permuted layout: ONE float4 gather per edge per warp. Depth-3 prefetch.
__global__ void __launch_bounds__(256) k_edge(const float* __restrict__ att,
                                              const float* __restrict__ bias) {
    __shared__ float att_s[FDIM];
    __shared__ float part[4][CDIM];
    int tid = threadIdx.x;
    for (int i = tid; i < FDIM; i += 256) att_s[i] = att[i];
    __syncthreads();

    int warp = tid >> 5, lane = tid & 31;
    int nodeLocal = warp >> 1;
    int hp = warp & 1;
    int gw = blockIdx.x * 4 + nodeLocal;   // NNODES = 12500*4 exactly
    int hbase = hp * 2;
    const size_t hoff = (size_t)hp * 256 + lane * 8;   // permuted: one float4

    // xr for this warp's 2 heads: one float4
    float4 xrv[2];
    {
        float4 raw = *(const float4*)(g_xrh + (size_t)gw * FDIM + hoff);
        __half2 h01 = *(__half2*)&raw.x, h23 = *(__half2*)&raw.y;
        float2 f01 = __half22float2(h01), f23 = __half22float2(h23);
        xrv[0] = make_float4(f01.x, f01.y, f23.x, f23.y);
        h01 = *(__half2*)&raw.z; h23 = *(__half2*)&raw.w;
        f01 = __half22float2(h01); f23 = __half22float2(h23);
        xrv[1] = make_float4(f01.x, f01.y, f23.x, f23.y);
    }

    float attv[8];
#pragma unroll
    for (int j = 0; j < 2; j++) {
        float4 a = *reinterpret_cast<const float4*>(&att_s[(hbase + j) * 128 + lane * 4]);
        attv[j * 4 + 0] = a.x; attv[j * 4 + 1] = a.y;
        attv[j * 4 + 2] = a.z; attv[j * 4 + 3] = a.w;
    }

    float den[2] = {0.f, 0.f};
    float acc[8];
#pragma unroll
    for (int i = 0; i < 8; i++) acc[i] = 0.f;

    int s0 = g_rowptr[gw], s1 = g_rowptr[gw + 1];

    // depth-3 prefetch ring of single float4s
    float4 pb0, pb1, pb2;
    if (s0 < s1)     pb0 = *(const float4*)(g_xlh + (size_t)g_srcs[s0] * FDIM + hoff);
    if (s0 + 1 < s1) pb1 = *(const float4*)(g_xlh + (size_t)g_srcs[s0 + 1] * FDIM + hoff);
    if (s0 + 2 < s1) pb2 = *(const float4*)(g_xlh + (size_t)g_srcs[s0 + 2] * FDIM + hoff);

    for (int k = s0; k < s1; k++) {
        float4 cur = pb0;
        pb0 = pb1; pb1 = pb2;
        if (k + 3 < s1)
            pb2 = *(const float4*)(g_xlh + (size_t)g_srcs[k + 3] * FDIM + hoff);

        float4 xlv[2];
        {
            __half2 h01 = *(__half2*)&cur.x, h23 = *(__half2*)&cur.y;
            float2 f01 = __half22float2(h01), f23 = __half22float2(h23);
            xlv[0] = make_float4(f01.x, f01.y, f23.x, f23.y);
            h01 = *(__half2*)&cur.z; h23 = *(__half2*)&cur.w;
            f01 = __half22float2(h01); f23 = __half22float2(h23);
            xlv[1] = make_float4(f01.x, f01.y, f23.x, f23.y);
        }

        float p[2];
#pragma unroll
        for (int j = 0; j < 2; j++) {
            p[j] = attv[j * 4 + 0] * lrelu(xlv[j].x + xrv[j].x)
                 + attv[j * 4 + 1] * lrelu(xlv[j].y + xrv[j].y)
                 + attv[j * 4 + 2] * lrelu(xlv[j].z + xrv[j].z)
                 + attv[j * 4 + 3] * lrelu(xlv[j].w + xrv[j].w);
        }
        // 8-shuffle joint reduction
        p[0] += __shfl_xor_sync(0xffffffffu, p[0], 16);
        p[1] += __shfl_xor_sync(0xffffffffu, p[1], 16);
        float v = (lane & 16) ? p[1] : p[0];
        v += __shfl_xor_sync(0xffffffffu, v, 8);
        v += __shfl_xor_sync(0xffffffffu, v, 4);
        v += __shfl_xor_sync(0xffffffffu, v, 2);
        v += __shfl_xor_sync(0xffffffffu, v, 1);
        float pw0 = __expf(fminf(__shfl_sync(0xffffffffu, v, 0), 60.f));
        float pw1 = __expf(fminf(__shfl_sync(0xffffffffu, v, 16), 60.f));

        den[0] += pw0;
        den[1] += pw1;
        acc[0] = fmaf(pw0, xlv[0].x, acc[0]);
        acc[1] = fmaf(pw0, xlv[0].y, acc[1]);
        acc[2] = fmaf(pw0, xlv[0].z, acc[2]);
        acc[3] = fmaf(pw0, xlv[0].w, acc[3]);
        acc[4] = fmaf(pw1, xlv[1].x, acc[4]);
        acc[5] = fmaf(pw1, xlv[1].y, acc[5]);
        acc[6] = fmaf(pw1, xlv[1].z, acc[6]);
        acc[7] = fmaf(pw1, xlv[1].w, acc[7]);
    }

    // partial head-mean over this warp's 2 heads
    float inv0 = (den[0] > 0.f) ? 0.25f / den[0] : 0.f;
    float inv1 = (den[1] > 0.f) ? 0.25f / den[1] : 0.f;
    float o0 = acc[0] * inv0 + acc[4] * inv1;
    float o1 = acc[1] * inv0 + acc[5] * inv1;
    float o2 = acc[2] * inv0 + acc[6] * inv1;
    float o3 = acc[3] * inv0 + acc[7] * inv1;

    if (hp == 1) {
        part[nodeLocal][lane * 4 + 0] = o0;
        part[nodeLocal][lane * 4 + 1] = o1;
        part[nodeLocal][lane * 4 + 2] = o2;
        part[nodeLocal][lane * 4 + 3] = o3;
    }
    __syncthreads();
    if (hp == 0) {
        o0 += part[nodeLocal][lane * 4 + 0];
        o1 += part[nodeLocal][lane * 4 + 1];
        o2 += part[nodeLocal][lane * 4 + 2];
        o3 += part[nodeLocal][lane * 4 + 3];

        float4 bv = *reinterpret_cast<const float4*>(&bias[lane * 4]);
        float4 out;
        out.x = elu(o0 + bv.x);
        out.y = elu(o1 + bv.y);
        out.z = elu(o2 + bv.z);
        out.w = elu(o3 + bv.w);
        *reinterpret_cast<float4*>(&g_h[(size_t)gw * CDIM + lane * 4]) = out;

        // bf16 hi/lo split for the next layer's tensor-core GEMM
        __nv_bfloat16 h0 = __float2bfloat16(out.x), h1 = __float2bfloat16(out.y);
        __nv_bfloat16 h2 = __float2bfloat16(out.z), h3 = __float2bfloat16(out.w);
        __nv_bfloat16 l0 = __float2bfloat16(out.x - __bfloat162float(h0));
        __nv_bfloat16 l1 = __float2bfloat16(out.y - __bfloat162float(h1));
        __nv_bfloat16 l2 = __float2bfloat16(out.z - __bfloat162float(h2));
        __nv_bfloat16 l3 = __float2bfloat16(out.w - __bfloat162float(h3));
        __nv_bfloat162 hpk[2] = {{h0, h1}, {h2, h3}};
        __nv_bfloat162 lpk[2] = {{l0, l1}, {l2, l3}};
        *reinterpret_cast<float2*>(&g_ah[(size_t)gw * 256 + lane * 4])       = *reinterpret_cast<float2*>(hpk);
        *reinterpret_cast<float2*>(&g_ah[(size_t)gw * 256 + 128 + lane * 4]) = *reinterpret_cast<float2*>(lpk);
    }
}

// ---------------- global mean pool (sum + count fused) + final linear ----------------
__global__ void k_pool_acc(const int* __restrict__ batch) {
    int c = threadIdx.x;           // 128 threads
    int n0 = blockIdx.x * 64;
    int n1 = min(n0 + 64, NNODES);
    if (n0 >= NNODES) return;
    float local = 0.f;
    int cnt = 0;
    int curg = batch[n0];
    for (int n = n0; n < n1; n++) {
        int g = batch[n];
        if (g != curg) {
            atomicAdd(&g_psum[curg * CDIM + c], local);
            if (c == 0) atomicAdd(&g_pcnt[curg], (float)cnt);
            local = 0.f; cnt = 0;
            curg = g;
        }
        local += g_h[(size_t)n * CDIM + c];
        cnt++;
    }
    atomicAdd(&g_psum[curg * CDIM + c], local);
    if (c == 0) atomicAdd(&g_pcnt[curg], (float)cnt);
}

__global__ void k_final(const float* __restrict__ W, const float* __restrict__ b,
                        float* __restrict__ out) {
    __shared__ float gsh[CDIM];
    int g = blockIdx.x;
    int j = threadIdx.x;
    float inv = 1.0f / fmaxf(g_pcnt[g], 1.0f);
    gsh[j] = g_psum[g * CDIM + j] * inv;
    __syncthreads();
    float acc = b[j];
    for (int k = 0; k < CDIM; k++) acc = fmaf(gsh[k], W[k * CDIM + j], acc);
    out[g * CDIM + j] = acc;
}

// ---------------- launcher ----------------
extern "C" void kernel_launch(void* const* d_in, const int* in_sizes, int n_in,
                              void* d_out, int out_size) {
    const float* x     = (const float*)d_in[0];
    const int*   ei    = (const int*)d_in[1];   // [2, E] int32
    const int*   batch = (const int*)d_in[2];

    const float* Wl[3] = {(const float*)d_in[3],  (const float*)d_in[9],  (const float*)d_in[15]};
    const float* bl[3] = {(const float*)d_in[4],  (const float*)d_in[10], (const float*)d_in[16]};
    const float* Wr[3] = {(const float*)d_in[5],  (const float*)d_in[11], (const float*)d_in[17]};
    const float* br[3] = {(const float*)d_in[6],  (const float*)d_in[12], (const float*)d_in[18]};
    const float* at[3] = {(const float*)d_in[7],  (const float*)d_in[13], (const float*)d_in[19]};
    const float* bb[3] = {(const float*)d_in[8],  (const float*)d_in[14], (const float*)d_in[20]};
    const float* linW  = (const float*)d_in[21];
    const float* linb  = (const float*)d_in[22];
    float* out = (float*)d_out;

    int E = in_sizes[1] / 2;
    int nb = (NNODES + 1023) / 1024;

    cudaFuncSetAttribute(k_gemm_mma, cudaFuncAttributeMaxDynamicSharedMemorySize, SMEM_GEMM);

    // CSR build (per replay; deterministic work)
    k_zero_all<<<(NNODES + 255) / 256, 256>>>();
    k_hist<<<(E + 255) / 256, 256>>>(ei, E);
    k_scan1<<<nb, 1024>>>();
    k_scan3<<<nb, 1024>>>();
    k_scatter<<<(E + 255) / 256, 256>>>(ei, E);

    // weight split prep (cheap)
    k_wprep<<<(384 * 512 + 255) / 256, 256>>>(Wl[1], Wr[1], Wl[2], Wr[2]);

    // layer 0
    k_lin0<<<(NNODES * 128 + 255) / 256, 256>>>(x, Wl[0], bl[0], Wr[0], br[0]);
    k_edge<<<NNODES / 4, 256>>>(at[0], bb[0]);

    // layers 1, 2: tensor-core split-bf16 GEMM then fused edge pass
    dim3 gg((NNODES + 127) / 128, 4, 2);
    k_gemm_mma<<<gg, 256, SMEM_GEMM>>>(0, bl[1], br[1]);
    k_edge<<<NNODES / 4, 256>>>(at[1], bb[1]);
    k_gemm_mma<<<gg, 256, SMEM_GEMM>>>(2, bl[2], br[2]);
    k_edge<<<NNODES / 4, 256>>>(at[2], bb[2]);

    // pool + final linear
    k_pool_acc<<<(NNODES + 63) / 64, 128>>>(batch);
    k_final<<<NGRAPHS, CDIM>>>(linW, linb, out);
}

// round 15
// speedup vs baseline: 1.1188x; 1.0296x over previous
#include <cuda_runtime.h>
#include <cuda_bf16.h>
#include <cuda_fp16.h>
#include <cstdint>
#include <math.h>

#define NNODES 50000
#define NEDGES 400000
#define NGRAPHS 64
#define FDIM 512      // HEADS * GAT_DIM
#define CDIM 128      // GAT_DIM
#define NEG_SLOPE 0.2f

// ---------------- device scratch (static, no allocation) ----------------
__device__ __half g_xlh[NNODES * FDIM];   // 50 MB (L2-resident gather target)
__device__ __half g_xrh[NNODES * FDIM];   // 50 MB
__device__ __nv_bfloat16 g_ah[NNODES * 256];   // hi (cols 0-127) | lo (cols 128-255)
__device__ __nv_bfloat16 g_wbig[4][384 * 512]; // split weights: Wl1,Wr1,Wl2,Wr2
__device__ int   g_deg[NNODES];
__device__ int   g_rowptr[NNODES + 1];
__device__ int   g_cur[NNODES];
__device__ int   g_srcs[NEDGES];
__device__ int   g_bsum[64];
__device__ float g_psum[NGRAPHS * CDIM];
__device__ float g_pcnt[NGRAPHS];

__device__ __forceinline__ float lrelu(float v) {
    return fmaxf(v, 0.0f) + NEG_SLOPE * fminf(v, 0.0f);
}
__device__ __forceinline__ float elu(float v) {
    return v > 0.0f ? v : expm1f(v);
}

// ---------------- CSR build ----------------
__global__ void k_zero_all() {
    int t = blockIdx.x * blockDim.x + threadIdx.x;
    if (t < NNODES) g_deg[t] = 0;
    if (t < NGRAPHS * CDIM) g_psum[t] = 0.0f;
    if (t < NGRAPHS) g_pcnt[t] = 0.0f;
}

__global__ void k_hist(const int* __restrict__ ei, int E) {
    int e = blockIdx.x * blockDim.x + threadIdx.x;
    if (e < E) atomicAdd(&g_deg[ei[E + e]], 1);
}

__global__ void k_scan1() {
    __shared__ int sh[1024];
    int i = blockIdx.x * 1024 + threadIdx.x;
    int v = (i < NNODES) ? g_deg[i] : 0;
    sh[threadIdx.x] = v;
    __syncthreads();
    for (int off = 1; off < 1024; off <<= 1) {
        int t = (threadIdx.x >= off) ? sh[threadIdx.x - off] : 0;
        __syncthreads();
        sh[threadIdx.x] += t;
        __syncthreads();
    }
    if (i < NNODES) g_rowptr[i] = sh[threadIdx.x] - v;
    if (threadIdx.x == 1023) g_bsum[blockIdx.x] = sh[1023];
}

// fused block-offset + apply
__global__ void k_scan3() {
    __shared__ int soff;
    int blk = blockIdx.x;
    if (threadIdx.x < 32) {
        int v = 0;
        if (threadIdx.x < blk) v = g_bsum[threadIdx.x];
        if (threadIdx.x + 32 < blk) v += g_bsum[threadIdx.x + 32];
#pragma unroll
        for (int o = 16; o; o >>= 1) v += __shfl_xor_sync(0xffffffffu, v, o);
        if (threadIdx.x == 0) {
            soff = v;
            if (blk == (int)gridDim.x - 1) g_rowptr[NNODES] = v + g_bsum[blk];
        }
    }
    __syncthreads();
    int i = blk * 1024 + threadIdx.x;
    if (i < NNODES) {
        int v = g_rowptr[i] + soff;
        g_rowptr[i] = v;
        g_cur[i] = v;
    }
}

__global__ void k_scatter(const int* __restrict__ ei, int E) {
    int e = blockIdx.x * blockDim.x + threadIdx.x;
    if (e < E) {
        int d = ei[E + e];
        int pos = atomicAdd(&g_cur[d], 1);
        g_srcs[pos] = ei[e];
    }
}

// ---------------- layer 0 transform (d_in = 3, memory bound) ----------------
__global__ void k_lin0(const float* __restrict__ x,
                       const float* __restrict__ Wl, const float* __restrict__ bl,
                       const float* __restrict__ Wr, const float* __restrict__ br) {
    int t = blockIdx.x * blockDim.x + threadIdx.x;
    int n = t >> 7;
    if (n >= NNODES) return;
    int j = (t & 127) * 4;
    float x0 = x[n * 3 + 0], x1 = x[n * 3 + 1], x2 = x[n * 3 + 2];

    float4 w0 = *(const float4*)(Wl + 0 * FDIM + j);
    float4 w1 = *(const float4*)(Wl + 1 * FDIM + j);
    float4 w2 = *(const float4*)(Wl + 2 * FDIM + j);
    float4 bb = *(const float4*)(bl + j);
    float4 o;
    o.x = bb.x + x0 * w0.x + x1 * w1.x + x2 * w2.x;
    o.y = bb.y + x0 * w0.y + x1 * w1.y + x2 * w2.y;
    o.z = bb.z + x0 * w0.z + x1 * w1.z + x2 * w2.z;
    o.w = bb.w + x0 * w0.w + x1 * w1.w + x2 * w2.w;
    {
        union { __half2 h[2]; uint2 u; } pk;
        pk.h[0] = __floats2half2_rn(o.x, o.y);
        pk.h[1] = __floats2half2_rn(o.z, o.w);
        *(uint2*)(g_xlh + (size_t)n * FDIM + j) = pk.u;
    }

    w0 = *(const float4*)(Wr + 0 * FDIM + j);
    w1 = *(const float4*)(Wr + 1 * FDIM + j);
    w2 = *(const float4*)(Wr + 2 * FDIM + j);
    bb = *(const float4*)(br + j);
    o.x = bb.x + x0 * w0.x + x1 * w1.x + x2 * w2.x;
    o.y = bb.y + x0 * w0.y + x1 * w1.y + x2 * w2.y;
    o.z = bb.z + x0 * w0.z + x1 * w1.z + x2 * w2.z;
    o.w = bb.w + x0 * w0.w + x1 * w1.w + x2 * w2.w;
    {
        union { __half2 h[2]; uint2 u; } pk;
        pk.h[0] = __floats2half2_rn(o.x, o.y);
        pk.h[1] = __floats2half2_rn(o.z, o.w);
        *(uint2*)(g_xrh + (size_t)n * FDIM + j) = pk.u;
    }
}

// ---------------- weight split prep: W[128,512] fp32 -> [384,512] bf16 ----------------
__global__ void k_wprep(const float* __restrict__ Wl1, const float* __restrict__ Wr1,
                        const float* __restrict__ Wl2, const float* __restrict__ Wr2) {
    int idx = blockIdx.x * 256 + threadIdx.x;
    if (idx >= 384 * 512) return;
    int r = idx >> 9, n = idx & 511;
    int sr = (r < 128) ? r : ((r < 256) ? r - 128 : r - 256);
    bool want_lo = (r >= 128 && r < 256);
    const float* Ws[4] = {Wl1, Wr1, Wl2, Wr2};
#pragma unroll
    for (int w = 0; w < 4; w++) {
        float v = Ws[w][sr * 512 + n];
        __nv_bfloat16 h = __float2bfloat16(v);
        g_wbig[w][idx] = want_lo ? __float2bfloat16(v - __bfloat162float(h)) : h;
    }
}

// ---------------- tensor-core GEMM ----------------
#define GM_AST 40
#define GM_BST 136
#define AS_STAGE_B (128 * GM_AST * 2)   // 10240 B
#define BS_STAGE_B (32 * GM_BST * 2)    // 8704 B
#define SMEM_GEMM (4 * AS_STAGE_B + 3 * BS_STAGE_B)   // 67072 B

__device__ __forceinline__ void ldsm_x4(uint32_t r[4], uint32_t addr) {
    asm volatile("ldmatrix.sync.aligned.m8n8.x4.shared.b16 {%0,%1,%2,%3}, [%4];"
                 : "=r"(r[0]), "=r"(r[1]), "=r"(r[2]), "=r"(r[3]) : "r"(addr));
}
__device__ __forceinline__ void ldsm_x4_t(uint32_t r[4], uint32_t addr) {
    asm volatile("ldmatrix.sync.aligned.m8n8.x4.trans.shared.b16 {%0,%1,%2,%3}, [%4];"
                 : "=r"(r[0]), "=r"(r[1]), "=r"(r[2]), "=r"(r[3]) : "r"(addr));
}
__device__ __forceinline__ void mma16816(float c[4], const uint32_t a[4],
                                         uint32_t b0, uint32_t b1) {
    asm volatile(
        "mma.sync.aligned.m16n8k16.row.col.f32.bf16.bf16.f32 "
        "{%0,%1,%2,%3}, {%4,%5,%6,%7}, {%8,%9}, {%0,%1,%2,%3};"
        : "+f"(c[0]), "+f"(c[1]), "+f"(c[2]), "+f"(c[3])
        : "r"(a[0]), "r"(a[1]), "r"(a[2]), "r"(a[3]), "r"(b0), "r"(b1));
}
__device__ __forceinline__ void cp16(uint32_t dst, const void* src, int sz) {
    asm volatile("cp.async.cg.shared.global [%0], [%1], 16, %2;"
                 :: "r"(dst), "l"(src), "r"(sz));
}

__global__ void __launch_bounds__(256) k_gemm_mma(int lbase,
                                                  const float* __restrict__ bl,
                                                  const float* __restrict__ br) {
    extern __shared__ __align__(16) char dynsm[];
    uint32_t as_base = (uint32_t)__cvta_generic_to_shared(dynsm);
    uint32_t bs_base = as_base + 4 * AS_STAGE_B;

    const __nv_bfloat16* wbig = g_wbig[lbase + blockIdx.z];
    const float* bias = blockIdx.z ? br : bl;
    __half* Cout = blockIdx.z ? g_xrh : g_xlh;

    int tid = threadIdx.x;
    int m0 = blockIdx.x * 128, n0 = blockIdx.y * 128;
    int warp = tid >> 5, lane = tid & 31;
    int wm = warp >> 1, wn = warp & 1;

    int ar[2], aq[2], brw[2], bq[2];
    int aok[2];
#pragma unroll
    for (int it = 0; it < 2; it++) {
        int s = tid + it * 256;
        ar[it] = s >> 2;  aq[it] = s & 3;
        brw[it] = s >> 4; bq[it] = s & 15;
        aok[it] = (m0 + ar[it]) < NNODES ? 16 : 0;
    }

    float c[2][8][4];
#pragma unroll
    for (int f = 0; f < 2; f++)
#pragma unroll
        for (int j = 0; j < 8; j++)
#pragma unroll
            for (int q = 0; q < 4; q++) c[f][j][q] = 0.0f;

    uint32_t a_ld[2][2], b_ld[4][2];
#pragma unroll
    for (int f = 0; f < 2; f++)
#pragma unroll
        for (int kh = 0; kh < 2; kh++)
            a_ld[f][kh] = as_base +
                ((wm * 32 + f * 16 + (lane & 15)) * GM_AST + kh * 16 + (lane >> 4) * 8) * 2;
#pragma unroll
    for (int g = 0; g < 4; g++)
#pragma unroll
        for (int kh = 0; kh < 2; kh++)
            b_ld[g][kh] = bs_base +
                ((kh * 16 + (lane & 15)) * GM_BST + wn * 64 + g * 16 + (lane >> 4) * 8) * 2;

    auto load_chunk = [&](int kt) {
        int aslot = kt & 3;
        int bslot = kt % 3;
        bool loadA = (kt < 4) || (kt >= 8);
        int acol = (kt < 8) ? (kt & 3) * 32 : ((kt - 8) * 32 + 128);
#pragma unroll
        for (int it = 0; it < 2; it++) {
            if (loadA)
                cp16(as_base + aslot * AS_STAGE_B + (ar[it] * GM_AST + aq[it] * 8) * 2,
                     g_ah + (size_t)(m0 + ar[it]) * 256 + acol + aq[it] * 8, aok[it]);
            cp16(bs_base + bslot * BS_STAGE_B + (brw[it] * GM_BST + bq[it] * 8) * 2,
                 wbig + (size_t)(kt * 32 + brw[it]) * 512 + n0 + bq[it] * 8, 16);
        }
    };

#pragma unroll
    for (int p = 0; p < 2; p++) {
        load_chunk(p);
        asm volatile("cp.async.commit_group;");
    }

    for (int kt = 0; kt < 12; kt++) {
        asm volatile("cp.async.wait_group 1;");
        __syncthreads();
        int soffA = (kt & 3) * AS_STAGE_B;
        int soffB = (kt % 3) * BS_STAGE_B;

        uint32_t a[2][2][4];
#pragma unroll
        for (int f = 0; f < 2; f++)
#pragma unroll
            for (int kh = 0; kh < 2; kh++)
                ldsm_x4(a[f][kh], a_ld[f][kh] + soffA);

        if (kt + 2 < 12) load_chunk(kt + 2);
        asm volatile("cp.async.commit_group;");

#pragma unroll
        for (int g = 0; g < 4; g++) {
            uint32_t b0[4], b1[4];
            ldsm_x4_t(b0, b_ld[g][0] + soffB);
            ldsm_x4_t(b1, b_ld[g][1] + soffB);
#pragma unroll
            for (int f = 0; f < 2; f++) {
                mma16816(c[f][2 * g],     a[f][0], b0[0], b0[1]);
                mma16816(c[f][2 * g + 1], a[f][0], b0[2], b0[3]);
                mma16816(c[f][2 * g],     a[f][1], b1[0], b1[1]);
                mma16816(c[f][2 * g + 1], a[f][1], b1[2], b1[3]);
            }
        }
    }

    // epilogue -> fp16
    int r0 = lane >> 2, cp = (lane & 3) * 2;
#pragma unroll
    for (int f = 0; f < 2; f++) {
        int gr = m0 + wm * 32 + f * 16 + r0;
#pragma unroll
        for (int j = 0; j < 8; j++) {
            int col = n0 + wn * 64 + j * 8 + cp;
            float b0v = bias[col], b1v = bias[col + 1];
            if (gr < NNODES) {
                __half2 o = __floats2half2_rn(c[f][j][0] + b0v, c[f][j][1] + b1v);
                *(__half2*)&Cout[(size_t)gr * FDIM + col] = o;
            }
            if (gr + 8 < NNODES) {
                __half2 o = __floats2half2_rn(c[f][j][2] + b0v, c[f][j][3] + b1v);
                *(__half2*)&Cout[(size_t)(gr + 8) * FDIM + col] = o;
            }
        }
    }
}

// ---------------- fused edge pass: direct-exp segment softmax ----------------
// TWO warps per destination node (head pair each). Block = 256 = 8 warps = 4 nodes.
// 8-shuffle joint reduction; depth-2 prefetch; no g_h store (pool reads g_ah).
__global__ void __launch_bounds__(256) k_edge(const float* __restrict__ att,
                                              const float* __restrict__ bias) {
    __shared__ float att_s[FDIM];
    __shared__ float part[4][CDIM];
    int tid = threadIdx.x;
    for (int i = tid; i < FDIM; i += 256) att_s[i] = att[i];
    __syncthreads();

    int warp = tid >> 5, lane = tid & 31;
    int nodeLocal = warp >> 1;
    int hp = warp & 1;
    int gw = blockIdx.x * 4 + nodeLocal;   // NNODES = 12500*4 exactly
    int hbase = hp * 2;

    float4 xrv[2];
#pragma unroll
    for (int j = 0; j < 2; j++) {
        float2 raw = *(const float2*)(g_xrh + (size_t)gw * FDIM + (hbase + j) * 128 + lane * 4);
        __half2 h01 = *(__half2*)&raw.x;
        __half2 h23 = *(__half2*)&raw.y;
        float2 f01 = __half22float2(h01), f23 = __half22float2(h23);
        xrv[j] = make_float4(f01.x, f01.y, f23.x, f23.y);
    }

    float attv[8];
#pragma unroll
    for (int j = 0; j < 2; j++) {
        float4 a = *reinterpret_cast<const float4*>(&att_s[(hbase + j) * 128 + lane * 4]);
        attv[j * 4 + 0] = a.x; attv[j * 4 + 1] = a.y;
        attv[j * 4 + 2] = a.z; attv[j * 4 + 3] = a.w;
    }

    float den[2] = {0.f, 0.f};
    float acc[8];
#pragma unroll
    for (int i = 0; i < 8; i++) acc[i] = 0.f;

    int s0 = g_rowptr[gw], s1 = g_rowptr[gw + 1];

    float2 nxt[2], nx2[2];
    if (s0 < s1) {
        const __half* xlp = g_xlh + (size_t)g_srcs[s0] * FDIM + hbase * 128 + lane * 4;
#pragma unroll
        for (int j = 0; j < 2; j++) nxt[j] = *(const float2*)(xlp + j * 128);
    }
    if (s0 + 1 < s1) {
        const __half* xlp = g_xlh + (size_t)g_srcs[s0 + 1] * FDIM + hbase * 128 + lane * 4;
#pragma unroll
        for (int j = 0; j < 2; j++) nx2[j] = *(const float2*)(xlp + j * 128);
    }

    for (int k = s0; k < s1; k++) {
        float4 xlv[2];
#pragma unroll
        for (int j = 0; j < 2; j++) {
            __half2 h01 = *(__half2*)&nxt[j].x;
            __half2 h23 = *(__half2*)&nxt[j].y;
            float2 f01 = __half22float2(h01), f23 = __half22float2(h23);
            xlv[j] = make_float4(f01.x, f01.y, f23.x, f23.y);
            nxt[j] = nx2[j];
        }
        if (k + 2 < s1) {
            const __half* xlp = g_xlh + (size_t)g_srcs[k + 2] * FDIM + hbase * 128 + lane * 4;
#pragma unroll
            for (int j = 0; j < 2; j++) nx2[j] = *(const float2*)(xlp + j * 128);
        }

        float p[2];
#pragma unroll
        for (int j = 0; j < 2; j++) {
            p[j] = attv[j * 4 + 0] * lrelu(xlv[j].x + xrv[j].x)
                 + attv[j * 4 + 1] * lrelu(xlv[j].y + xrv[j].y)
                 + attv[j * 4 + 2] * lrelu(xlv[j].z + xrv[j].z)
                 + attv[j * 4 + 3] * lrelu(xlv[j].w + xrv[j].w);
        }
        // 8-shuffle joint reduction
        p[0] += __shfl_xor_sync(0xffffffffu, p[0], 16);
        p[1] += __shfl_xor_sync(0xffffffffu, p[1], 16);
        float v = (lane & 16) ? p[1] : p[0];
        v += __shfl_xor_sync(0xffffffffu, v, 8);
        v += __shfl_xor_sync(0xffffffffu, v, 4);
        v += __shfl_xor_sync(0xffffffffu, v, 2);
        v += __shfl_xor_sync(0xffffffffu, v, 1);
        float pw0 = __expf(fminf(__shfl_sync(0xffffffffu, v, 0), 60.f));
        float pw1 = __expf(fminf(__shfl_sync(0xffffffffu, v, 16), 60.f));

        den[0] += pw0;
        den[1] += pw1;
        acc[0] = fmaf(pw0, xlv[0].x, acc[0]);
        acc[1] = fmaf(pw0, xlv[0].y, acc[1]);
        acc[2] = fmaf(pw0, xlv[0].z, acc[2]);
        acc[3] = fmaf(pw0, xlv[0].w, acc[3]);
        acc[4] = fmaf(pw1, xlv[1].x, acc[4]);
        acc[5] = fmaf(pw1, xlv[1].y, acc[5]);
        acc[6] = fmaf(pw1, xlv[1].z, acc[6]);
        acc[7] = fmaf(pw1, xlv[1].w, acc[7]);
    }

    // partial head-mean over this warp's 2 heads
    float inv0 = (den[0] > 0.f) ? 0.25f / den[0] : 0.f;
    float inv1 = (den[1] > 0.f) ? 0.25f / den[1] : 0.f;
    float o0 = acc[0] * inv0 + acc[4] * inv1;
    float o1 = acc[1] * inv0 + acc[5] * inv1;
    float o2 = acc[2] * inv0 + acc[6] * inv1;
    float o3 = acc[3] * inv0 + acc[7] * inv1;

    if (hp == 1) {
        part[nodeLocal][lane * 4 + 0] = o0;
        part[nodeLocal][lane * 4 + 1] = o1;
        part[nodeLocal][lane * 4 + 2] = o2;
        part[nodeLocal][lane * 4 + 3] = o3;
    }
    __syncthreads();
    if (hp == 0) {
        o0 += part[nodeLocal][lane * 4 + 0];
        o1 += part[nodeLocal][lane * 4 + 1];
        o2 += part[nodeLocal][lane * 4 + 2];
        o3 += part[nodeLocal][lane * 4 + 3];

        float4 bv = *reinterpret_cast<const float4*>(&bias[lane * 4]);
        float4 out;
        out.x = elu(o0 + bv.x);
        out.y = elu(o1 + bv.y);
        out.z = elu(o2 + bv.z);
        out.w = elu(o3 + bv.w);

        // bf16 hi/lo split: consumed by next GEMM and by the pool (hi+lo)
        __nv_bfloat16 h0 = __float2bfloat16(out.x), h1 = __float2bfloat16(out.y);
        __nv_bfloat16 h2 = __float2bfloat16(out.z), h3 = __float2bfloat16(out.w);
        __nv_bfloat16 l0 = __float2bfloat16(out.x - __bfloat162float(h0));
        __nv_bfloat16 l1 = __float2bfloat16(out.y - __bfloat162float(h1));
        __nv_bfloat16 l2 = __float2bfloat16(out.z - __bfloat162float(h2));
        __nv_bfloat16 l3 = __float2bfloat16(out.w - __bfloat162float(h3));
        __nv_bfloat162 hpk[2] = {{h0, h1}, {h2, h3}};
        __nv_bfloat162 lpk[2] = {{l0, l1}, {l2, l3}};
        *reinterpret_cast<float2*>(&g_ah[(size_t)gw * 256 + lane * 4])       = *reinterpret_cast<float2*>(hpk);
        *reinterpret_cast<float2*>(&g_ah[(size_t)gw * 256 + 128 + lane * 4]) = *reinterpret_cast<float2*>(lpk);
    }
}

// ---------------- global mean pool (reads hi+lo from g_ah) + final linear ----------------
__global__ void k_pool_acc(const int* __restrict__ batch) {
    int c = threadIdx.x;           // 128 threads
    int n0 = blockIdx.x * 64;
    int n1 = min(n0 + 64, NNODES);
    if (n0 >= NNODES) return;
    float local = 0.f;
    int cnt = 0;
    int curg = batch[n0];
    for (int n = n0; n < n1; n++) {
        int g = batch[n];
        if (g != curg) {
            atomicAdd(&g_psum[curg * CDIM + c], local);
            if (c == 0) atomicAdd(&g_pcnt[curg], (float)cnt);
            local = 0.f; cnt = 0;
            curg = g;
        }
        float hi = __bfloat162float(g_ah[(size_t)n * 256 + c]);
        float lo = __bfloat162float(g_ah[(size_t)n * 256 + 128 + c]);
        local += hi + lo;
        cnt++;
    }
    atomicAdd(&g_psum[curg * CDIM + c], local);
    if (c == 0) atomicAdd(&g_pcnt[curg], (float)cnt);
}

__global__ void k_final(const float* __restrict__ W, const float* __restrict__ b,
                        float* __restrict__ out) {
    __shared__ float gsh[CDIM];
    int g = blockIdx.x;
    int j = threadIdx.x;
    float inv = 1.0f / fmaxf(g_pcnt[g], 1.0f);
    gsh[j] = g_psum[g * CDIM + j] * inv;
    __syncthreads();
    float acc = b[j];
    for (int k = 0; k < CDIM; k++) acc = fmaf(gsh[k], W[k * CDIM + j], acc);
    out[g * CDIM + j] = acc;
}

// ---------------- launcher ----------------
extern "C" void kernel_launch(void* const* d_in, const int* in_sizes, int n_in,
                              void* d_out, int out_size) {
    const float* x     = (const float*)d_in[0];
    const int*   ei    = (const int*)d_in[1];   // [2, E] int32
    const int*   batch = (const int*)d_in[2];

    const float* Wl[3] = {(const float*)d_in[3],  (const float*)d_in[9],  (const float*)d_in[15]};
    const float* bl[3] = {(const float*)d_in[4],  (const float*)d_in[10], (const float*)d_in[16]};
    const float* Wr[3] = {(const float*)d_in[5],  (const float*)d_in[11], (const float*)d_in[17]};
    const float* br[3] = {(const float*)d_in[6],  (const float*)d_in[12], (const float*)d_in[18]};
    const float* at[3] = {(const float*)d_in[7],  (const float*)d_in[13], (const float*)d_in[19]};
    const float* bb[3] = {(const float*)d_in[8],  (const float*)d_in[14], (const float*)d_in[20]};
    const float* linW  = (const float*)d_in[21];
    const float* linb  = (const float*)d_in[22];
    float* out = (float*)d_out;

    int E = in_sizes[1] / 2;
    int nb = (NNODES + 1023) / 1024;

    cudaFuncSetAttribute(k_gemm_mma, cudaFuncAttributeMaxDynamicSharedMemorySize, SMEM_GEMM);

    // CSR build (per replay; deterministic work)
    k_zero_all<<<(NNODES + 255) / 256, 256>>>();
    k_hist<<<(E + 255) / 256, 256>>>(ei, E);
    k_scan1<<<nb, 1024>>>();
    k_scan3<<<nb, 1024>>>();
    k_scatter<<<(E + 255) / 256, 256>>>(ei, E);

    // weight split prep (cheap)
    k_wprep<<<(384 * 512 + 255) / 256, 256>>>(Wl[1], Wr[1], Wl[2], Wr[2]);

    // layer 0
    k_lin0<<<(NNODES * 128 + 255) / 256, 256>>>(x, Wl[0], bl[0], Wr[0], br[0]);
    k_edge<<<NNODES / 4, 256>>>(at[0], bb[0]);

    // layers 1, 2: tensor-core split-bf16 GEMM then fused edge pass
    dim3 gg((NNODES + 127) / 128, 4, 2);
    k_gemm_mma<<<gg, 256, SMEM_GEMM>>>(0, bl[1], br[1]);
    k_edge<<<NNODES / 4, 256>>>(at[1], bb[1]);
    k_gemm_mma<<<gg, 256, SMEM_GEMM>>>(2, bl[2], br[2]);
    k_edge<<<NNODES / 4, 256>>>(at[2], bb[2]);

    // pool + final linear
    k_pool_acc<<<(NNODES + 63) / 64, 128>>>(batch);
    k_final<<<NGRAPHS, CDIM>>>(linW, linb, out);
}

// round 16
// speedup vs baseline: 1.2246x; 1.0946x over previous
#include <cuda_runtime.h>
#include <cuda_bf16.h>
#include <cuda_fp16.h>
#include <cstdint>
#include <math.h>

#define NNODES 50000
#define NEDGES 400000
#define NGRAPHS 64
#define FDIM 512      // HEADS * GAT_DIM
#define CDIM 128      // GAT_DIM
#define NEG_SLOPE 0.2f

// ---------------- device scratch (static, no allocation) ----------------
__device__ __half g_xlh[NNODES * FDIM];   // 50 MB (L2-resident gather target)
__device__ __half g_xrh[NNODES * FDIM];   // 50 MB
__device__ __nv_bfloat16 g_ah[NNODES * 256];   // hi (cols 0-127) | lo (cols 128-255)
__device__ __nv_bfloat16 g_wbig[4][384 * 512]; // split weights: Wl1,Wr1,Wl2,Wr2
__device__ int   g_deg[NNODES];
__device__ int   g_rowptr[NNODES + 1];
__device__ int   g_cur[NNODES];
__device__ int   g_srcs[NEDGES];
__device__ int   g_bsum[64];
__device__ float g_psum[NGRAPHS * CDIM];
__device__ float g_pcnt[NGRAPHS];

__device__ __forceinline__ float lrelu(float v) {
    return fmaxf(v, 0.0f) + NEG_SLOPE * fminf(v, 0.0f);
}
__device__ __forceinline__ float elu(float v) {
    return v > 0.0f ? v : expm1f(v);
}

// ---------------- CSR build ----------------
__global__ void k_zero_all() {
    int t = blockIdx.x * blockDim.x + threadIdx.x;
    if (t < NNODES) g_deg[t] = 0;
    if (t < NGRAPHS * CDIM) g_psum[t] = 0.0f;
    if (t < NGRAPHS) g_pcnt[t] = 0.0f;
}

__global__ void k_hist(const int* __restrict__ ei, int E) {
    int e = blockIdx.x * blockDim.x + threadIdx.x;
    if (e < E) atomicAdd(&g_deg[ei[E + e]], 1);
}

__global__ void k_scan1() {
    __shared__ int sh[1024];
    int i = blockIdx.x * 1024 + threadIdx.x;
    int v = (i < NNODES) ? g_deg[i] : 0;
    sh[threadIdx.x] = v;
    __syncthreads();
    for (int off = 1; off < 1024; off <<= 1) {
        int t = (threadIdx.x >= off) ? sh[threadIdx.x - off] : 0;
        __syncthreads();
        sh[threadIdx.x] += t;
        __syncthreads();
    }
    if (i < NNODES) g_rowptr[i] = sh[threadIdx.x] - v;
    if (threadIdx.x == 1023) g_bsum[blockIdx.x] = sh[1023];
}

// fused block-offset + apply
__global__ void k_scan3() {
    __shared__ int soff;
    int blk = blockIdx.x;
    if (threadIdx.x < 32) {
        int v = 0;
        if (threadIdx.x < blk) v = g_bsum[threadIdx.x];
        if (threadIdx.x + 32 < blk) v += g_bsum[threadIdx.x + 32];
#pragma unroll
        for (int o = 16; o; o >>= 1) v += __shfl_xor_sync(0xffffffffu, v, o);
        if (threadIdx.x == 0) {
            soff = v;
            if (blk == (int)gridDim.x - 1) g_rowptr[NNODES] = v + g_bsum[blk];
        }
    }
    __syncthreads();
    int i = blk * 1024 + threadIdx.x;
    if (i < NNODES) {
        int v = g_rowptr[i] + soff;
        g_rowptr[i] = v;
        g_cur[i] = v;
    }
}

__global__ void k_scatter(const int* __restrict__ ei, int E) {
    int e = blockIdx.x * blockDim.x + threadIdx.x;
    if (e < E) {
        int d = ei[E + e];
        int pos = atomicAdd(&g_cur[d], 1);
        g_srcs[pos] = ei[e];
    }
}

// ---------------- layer 0 transform (d_in = 3, memory bound) ----------------
__global__ void k_lin0(const float* __restrict__ x,
                       const float* __restrict__ Wl, const float* __restrict__ bl,
                       const float* __restrict__ Wr, const float* __restrict__ br) {
    int t = blockIdx.x * blockDim.x + threadIdx.x;
    int n = t >> 7;
    if (n >= NNODES) return;
    int j = (t & 127) * 4;
    float x0 = x[n * 3 + 0], x1 = x[n * 3 + 1], x2 = x[n * 3 + 2];

    float4 w0 = *(const float4*)(Wl + 0 * FDIM + j);
    float4 w1 = *(const float4*)(Wl + 1 * FDIM + j);
    float4 w2 = *(const float4*)(Wl + 2 * FDIM + j);
    float4 bb = *(const float4*)(bl + j);
    float4 o;
    o.x = bb.x + x0 * w0.x + x1 * w1.x + x2 * w2.x;
    o.y = bb.y + x0 * w0.y + x1 * w1.y + x2 * w2.y;
    o.z = bb.z + x0 * w0.z + x1 * w1.z + x2 * w2.z;
    o.w = bb.w + x0 * w0.w + x1 * w1.w + x2 * w2.w;
    {
        union { __half2 h[2]; uint2 u; } pk;
        pk.h[0] = __floats2half2_rn(o.x, o.y);
        pk.h[1] = __floats2half2_rn(o.z, o.w);
        *(uint2*)(g_xlh + (size_t)n * FDIM + j) = pk.u;
    }

    w0 = *(const float4*)(Wr + 0 * FDIM + j);
    w1 = *(const float4*)(Wr + 1 * FDIM + j);
    w2 = *(const float4*)(Wr + 2 * FDIM + j);
    bb = *(const float4*)(br + j);
    o.x = bb.x + x0 * w0.x + x1 * w1.x + x2 * w2.x;
    o.y = bb.y + x0 * w0.y + x1 * w1.y + x2 * w2.y;
    o.z = bb.z + x0 * w0.z + x1 * w1.z + x2 * w2.z;
    o.w = bb.w + x0 * w0.w + x1 * w1.w + x2 * w2.w;
    {
        union { __half2 h[2]; uint2 u; } pk;
        pk.h[0] = __floats2half2_rn(o.x, o.y);
        pk.h[1] = __floats2half2_rn(o.z, o.w);
        *(uint2*)(g_xrh + (size_t)n * FDIM + j) = pk.u;
    }
}

// ---------------- weight split prep: W[128,512] fp32 -> [384,512] bf16 ----------------
__global__ void k_wprep(const float* __restrict__ Wl1, const float* __restrict__ Wr1,
                        const float* __restrict__ Wl2, const float* __restrict__ Wr2) {
    int idx = blockIdx.x * 256 + threadIdx.x;
    if (idx >= 384 * 512) return;
    int r = idx >> 9, n = idx & 511;
    int sr = (r < 128) ? r : ((r < 256) ? r - 128 : r - 256);
    bool want_lo = (r >= 128 && r < 256);
    const float* Ws[4] = {Wl1, Wr1, Wl2, Wr2};
#pragma unroll
    for (int w = 0; w < 4; w++) {
        float v = Ws[w][sr * 512 + n];
        __nv_bfloat16 h = __float2bfloat16(v);
        g_wbig[w][idx] = want_lo ? __float2bfloat16(v - __bfloat162float(h)) : h;
    }
}

// ---------------- tensor-core GEMM ----------------
#define GM_AST 40
#define GM_BST 136
#define AS_STAGE_B (128 * GM_AST * 2)   // 10240 B
#define BS_STAGE_B (32 * GM_BST * 2)    // 8704 B
#define SMEM_GEMM (4 * AS_STAGE_B + 3 * BS_STAGE_B)   // 67072 B

__device__ __forceinline__ void ldsm_x4(uint32_t r[4], uint32_t addr) {
    asm volatile("ldmatrix.sync.aligned.m8n8.x4.shared.b16 {%0,%1,%2,%3}, [%4];"
                 : "=r"(r[0]), "=r"(r[1]), "=r"(r[2]), "=r"(r[3]) : "r"(addr));
}
__device__ __forceinline__ void ldsm_x4_t(uint32_t r[4], uint32_t addr) {
    asm volatile("ldmatrix.sync.aligned.m8n8.x4.trans.shared.b16 {%0,%1,%2,%3}, [%4];"
                 : "=r"(r[0]), "=r"(r[1]), "=r"(r[2]), "=r"(r[3]) : "r"(addr));
}
__device__ __forceinline__ void mma16816(float c[4], const uint32_t a[4],
                                         uint32_t b0, uint32_t b1) {
    asm volatile(
        "mma.sync.aligned.m16n8k16.row.col.f32.bf16.bf16.f32 "
        "{%0,%1,%2,%3}, {%4,%5,%6,%7}, {%8,%9}, {%0,%1,%2,%3};"
        : "+f"(c[0]), "+f"(c[1]), "+f"(c[2]), "+f"(c[3])
        : "r"(a[0]), "r"(a[1]), "r"(a[2]), "r"(a[3]), "r"(b0), "r"(b1));
}
__device__ __forceinline__ void cp16(uint32_t dst, const void* src, int sz) {
    asm volatile("cp.async.cg.shared.global [%0], [%1], 16, %2;"
                 :: "r"(dst), "l"(src), "r"(sz));
}

__global__ void __launch_bounds__(256) k_gemm_mma(int lbase,
                                                  const float* __restrict__ bl,
                                                  const float* __restrict__ br) {
    extern __shared__ __align__(16) char dynsm[];
    uint32_t as_base = (uint32_t)__cvta_generic_to_shared(dynsm);
    uint32_t bs_base = as_base + 4 * AS_STAGE_B;

    const __nv_bfloat16* wbig = g_wbig[lbase + blockIdx.z];
    const float* bias = blockIdx.z ? br : bl;
    __half* Cout = blockIdx.z ? g_xrh : g_xlh;

    int tid = threadIdx.x;
    int m0 = blockIdx.x * 128, n0 = blockIdx.y * 128;
    int warp = tid >> 5, lane = tid & 31;
    int wm = warp >> 1, wn = warp & 1;

    int ar[2], aq[2], brw[2], bq[2];
    int aok[2];
#pragma unroll
    for (int it = 0; it < 2; it++) {
        int s = tid + it * 256;
        ar[it] = s >> 2;  aq[it] = s & 3;
        brw[it] = s >> 4; bq[it] = s & 15;
        aok[it] = (m0 + ar[it]) < NNODES ? 16 : 0;
    }

    float c[2][8][4];
#pragma unroll
    for (int f = 0; f < 2; f++)
#pragma unroll
        for (int j = 0; j < 8; j++)
#pragma unroll
            for (int q = 0; q < 4; q++) c[f][j][q] = 0.0f;

    uint32_t a_ld[2][2], b_ld[4][2];
#pragma unroll
    for (int f = 0; f < 2; f++)
#pragma unroll
        for (int kh = 0; kh < 2; kh++)
            a_ld[f][kh] = as_base +
                ((wm * 32 + f * 16 + (lane & 15)) * GM_AST + kh * 16 + (lane >> 4) * 8) * 2;
#pragma unroll
    for (int g = 0; g < 4; g++)
#pragma unroll
        for (int kh = 0; kh < 2; kh++)
            b_ld[g][kh] = bs_base +
                ((kh * 16 + (lane & 15)) * GM_BST + wn * 64 + g * 16 + (lane >> 4) * 8) * 2;

    auto load_chunk = [&](int kt) {
        int aslot = kt & 3;
        int bslot = kt % 3;
        bool loadA = (kt < 4) || (kt >= 8);
        int acol = (kt < 8) ? (kt & 3) * 32 : ((kt - 8) * 32 + 128);
#pragma unroll
        for (int it = 0; it < 2; it++) {
            if (loadA)
                cp16(as_base + aslot * AS_STAGE_B + (ar[it] * GM_AST + aq[it] * 8) * 2,
                     g_ah + (size_t)(m0 + ar[it]) * 256 + acol + aq[it] * 8, aok[it]);
            cp16(bs_base + bslot * BS_STAGE_B + (brw[it] * GM_BST + bq[it] * 8) * 2,
                 wbig + (size_t)(kt * 32 + brw[it]) * 512 + n0 + bq[it] * 8, 16);
        }
    };

#pragma unroll
    for (int p = 0; p < 2; p++) {
        load_chunk(p);
        asm volatile("cp.async.commit_group;");
    }

    for (int kt = 0; kt < 12; kt++) {
        asm volatile("cp.async.wait_group 1;");
        __syncthreads();
        int soffA = (kt & 3) * AS_STAGE_B;
        int soffB = (kt % 3) * BS_STAGE_B;

        uint32_t a[2][2][4];
#pragma unroll
        for (int f = 0; f < 2; f++)
#pragma unroll
            for (int kh = 0; kh < 2; kh++)
                ldsm_x4(a[f][kh], a_ld[f][kh] + soffA);

        if (kt + 2 < 12) load_chunk(kt + 2);
        asm volatile("cp.async.commit_group;");

#pragma unroll
        for (int g = 0; g < 4; g++) {
            uint32_t b0[4], b1[4];
            ldsm_x4_t(b0, b_ld[g][0] + soffB);
            ldsm_x4_t(b1, b_ld[g][1] + soffB);
#pragma unroll
            for (int f = 0; f < 2; f++) {
                mma16816(c[f][2 * g],     a[f][0], b0[0], b0[1]);
                mma16816(c[f][2 * g + 1], a[f][0], b0[2], b0[3]);
                mma16816(c[f][2 * g],     a[f][1], b1[0], b1[1]);
                mma16816(c[f][2 * g + 1], a[f][1], b1[2], b1[3]);
            }
        }
    }

    // epilogue -> fp16
    int r0 = lane >> 2, cp = (lane & 3) * 2;
#pragma unroll
    for (int f = 0; f < 2; f++) {
        int gr = m0 + wm * 32 + f * 16 + r0;
#pragma unroll
        for (int j = 0; j < 8; j++) {
            int col = n0 + wn * 64 + j * 8 + cp;
            float b0v = bias[col], b1v = bias[col + 1];
            if (gr < NNODES) {
                __half2 o = __floats2half2_rn(c[f][j][0] + b0v, c[f][j][1] + b1v);
                *(__half2*)&Cout[(size_t)gr * FDIM + col] = o;
            }
            if (gr + 8 < NNODES) {
                __half2 o = __floats2half2_rn(c[f][j][2] + b0v, c[f][j][3] + b1v);
                *(__half2*)&Cout[(size_t)(gr + 8) * FDIM + col] = o;
            }
        }
    }
}

// ---------------- fused edge pass: direct-exp segment softmax ----------------
// ONE node per 64-thread block (2 warps, head pair each). Block residency equals
// its own node's degree => no straggler coupling across nodes. att read directly
// from global (L1-broadcast), no smem staging.
__global__ void __launch_bounds__(64) k_edge(const float* __restrict__ att,
                                             const float* __restrict__ bias) {
    __shared__ float part[CDIM];
    int tid = threadIdx.x;
    int hp = tid >> 5, lane = tid & 31;
    int gw = blockIdx.x;                // grid = NNODES
    int hbase = hp * 2;

    float4 xrv[2];
#pragma unroll
    for (int j = 0; j < 2; j++) {
        float2 raw = *(const float2*)(g_xrh + (size_t)gw * FDIM + (hbase + j) * 128 + lane * 4);
        __half2 h01 = *(__half2*)&raw.x;
        __half2 h23 = *(__half2*)&raw.y;
        float2 f01 = __half22float2(h01), f23 = __half22float2(h23);
        xrv[j] = make_float4(f01.x, f01.y, f23.x, f23.y);
    }

    float attv[8];
#pragma unroll
    for (int j = 0; j < 2; j++) {
        float4 a = *reinterpret_cast<const float4*>(&att[(hbase + j) * 128 + lane * 4]);
        attv[j * 4 + 0] = a.x; attv[j * 4 + 1] = a.y;
        attv[j * 4 + 2] = a.z; attv[j * 4 + 3] = a.w;
    }

    float den[2] = {0.f, 0.f};
    float acc[8];
#pragma unroll
    for (int i = 0; i < 8; i++) acc[i] = 0.f;

    int s0 = g_rowptr[gw], s1 = g_rowptr[gw + 1];

    float2 nxt[2], nx2[2];
    if (s0 < s1) {
        const __half* xlp = g_xlh + (size_t)g_srcs[s0] * FDIM + hbase * 128 + lane * 4;
#pragma unroll
        for (int j = 0; j < 2; j++) nxt[j] = *(const float2*)(xlp + j * 128);
    }
    if (s0 + 1 < s1) {
        const __half* xlp = g_xlh + (size_t)g_srcs[s0 + 1] * FDIM + hbase * 128 + lane * 4;
#pragma unroll
        for (int j = 0; j < 2; j++) nx2[j] = *(const float2*)(xlp + j * 128);
    }

    for (int k = s0; k < s1; k++) {
        float4 xlv[2];
#pragma unroll
        for (int j = 0; j < 2; j++) {
            __half2 h01 = *(__half2*)&nxt[j].x;
            __half2 h23 = *(__half2*)&nxt[j].y;
            float2 f01 = __half22float2(h01), f23 = __half22float2(h23);
            xlv[j] = make_float4(f01.x, f01.y, f23.x, f23.y);
            nxt[j] = nx2[j];
        }
        if (k + 2 < s1) {
            const __half* xlp = g_xlh + (size_t)g_srcs[k + 2] * FDIM + hbase * 128 + lane * 4;
#pragma unroll
            for (int j = 0; j < 2; j++) nx2[j] = *(const float2*)(xlp + j * 128);
        }

        float p[2];
#pragma unroll
        for (int j = 0; j < 2; j++) {
            p[j] = attv[j * 4 + 0] * lrelu(xlv[j].x + xrv[j].x)
                 + attv[j * 4 + 1] * lrelu(xlv[j].y + xrv[j].y)
                 + attv[j * 4 + 2] * lrelu(xlv[j].z + xrv[j].z)
                 + attv[j * 4 + 3] * lrelu(xlv[j].w + xrv[j].w);
        }
        // 8-shuffle joint reduction
        p[0] += __shfl_xor_sync(0xffffffffu, p[0], 16);
        p[1] += __shfl_xor_sync(0xffffffffu, p[1], 16);
        float v = (lane & 16) ? p[1] : p[0];
        v += __shfl_xor_sync(0xffffffffu, v, 8);
        v += __shfl_xor_sync(0xffffffffu, v, 4);
        v += __shfl_xor_sync(0xffffffffu, v, 2);
        v += __shfl_xor_sync(0xffffffffu, v, 1);
        float pw0 = __expf(fminf(__shfl_sync(0xffffffffu, v, 0), 60.f));
        float pw1 = __expf(fminf(__shfl_sync(0xffffffffu, v, 16), 60.f));

        den[0] += pw0;
        den[1] += pw1;
        acc[0] = fmaf(pw0, xlv[0].x, acc[0]);
        acc[1] = fmaf(pw0, xlv[0].y, acc[1]);
        acc[2] = fmaf(pw0, xlv[0].z, acc[2]);
        acc[3] = fmaf(pw0, xlv[0].w, acc[3]);
        acc[4] = fmaf(pw1, xlv[1].x, acc[4]);
        acc[5] = fmaf(pw1, xlv[1].y, acc[5]);
        acc[6] = fmaf(pw1, xlv[1].z, acc[6]);
        acc[7] = fmaf(pw1, xlv[1].w, acc[7]);
    }

    // partial head-mean over this warp's 2 heads
    float inv0 = (den[0] > 0.f) ? 0.25f / den[0] : 0.f;
    float inv1 = (den[1] > 0.f) ? 0.25f / den[1] : 0.f;
    float o0 = acc[0] * inv0 + acc[4] * inv1;
    float o1 = acc[1] * inv0 + acc[5] * inv1;
    float o2 = acc[2] * inv0 + acc[6] * inv1;
    float o3 = acc[3] * inv0 + acc[7] * inv1;

    if (hp == 1) {
        part[lane * 4 + 0] = o0;
        part[lane * 4 + 1] = o1;
        part[lane * 4 + 2] = o2;
        part[lane * 4 + 3] = o3;
    }
    __syncthreads();
    if (hp == 0) {
        o0 += part[lane * 4 + 0];
        o1 += part[lane * 4 + 1];
        o2 += part[lane * 4 + 2];
        o3 += part[lane * 4 + 3];

        float4 bv = *reinterpret_cast<const float4*>(&bias[lane * 4]);
        float4 out;
        out.x = elu(o0 + bv.x);
        out.y = elu(o1 + bv.y);
        out.z = elu(o2 + bv.z);
        out.w = elu(o3 + bv.w);

        // bf16 hi/lo split: consumed by next GEMM and by the pool (hi+lo)
        __nv_bfloat16 h0 = __float2bfloat16(out.x), h1 = __float2bfloat16(out.y);
        __nv_bfloat16 h2 = __float2bfloat16(out.z), h3 = __float2bfloat16(out.w);
        __nv_bfloat16 l0 = __float2bfloat16(out.x - __bfloat162float(h0));
        __nv_bfloat16 l1 = __float2bfloat16(out.y - __bfloat162float(h1));
        __nv_bfloat16 l2 = __float2bfloat16(out.z - __bfloat162float(h2));
        __nv_bfloat16 l3 = __float2bfloat16(out.w - __bfloat162float(h3));
        __nv_bfloat162 hpk[2] = {{h0, h1}, {h2, h3}};
        __nv_bfloat162 lpk[2] = {{l0, l1}, {l2, l3}};
        *reinterpret_cast<float2*>(&g_ah[(size_t)gw * 256 + lane * 4])       = *reinterpret_cast<float2*>(hpk);
        *reinterpret_cast<float2*>(&g_ah[(size_t)gw * 256 + 128 + lane * 4]) = *reinterpret_cast<float2*>(lpk);
    }
}

// ---------------- global mean pool (reads hi+lo from g_ah) + final linear ----------------
__global__ void k_pool_acc(const int* __restrict__ batch) {
    int c = threadIdx.x;           // 128 threads
    int n0 = blockIdx.x * 64;
    int n1 = min(n0 + 64, NNODES);
    if (n0 >= NNODES) return;
    float local = 0.f;
    int cnt = 0;
    int curg = batch[n0];
    for (int n = n0; n < n1; n++) {
        int g = batch[n];
        if (g != curg) {
            atomicAdd(&g_psum[curg * CDIM + c], local);
            if (c == 0) atomicAdd(&g_pcnt[curg], (float)cnt);
            local = 0.f; cnt = 0;
            curg = g;
        }
        float hi = __bfloat162float(g_ah[(size_t)n * 256 + c]);
        float lo = __bfloat162float(g_ah[(size_t)n * 256 + 128 + c]);
        local += hi + lo;
        cnt++;
    }
    atomicAdd(&g_psum[curg * CDIM + c], local);
    if (c == 0) atomicAdd(&g_pcnt[curg], (float)cnt);
}

__global__ void k_final(const float* __restrict__ W, const float* __restrict__ b,
                        float* __restrict__ out) {
    __shared__ float gsh[CDIM];
    int g = blockIdx.x;
    int j = threadIdx.x;
    float inv = 1.0f / fmaxf(g_pcnt[g], 1.0f);
    gsh[j] = g_psum[g * CDIM + j] * inv;
    __syncthreads();
    float acc = b[j];
    for (int k = 0; k < CDIM; k++) acc = fmaf(gsh[k], W[k * CDIM + j], acc);
    out[g * CDIM + j] = acc;
}

// ---------------- launcher ----------------
extern "C" void kernel_launch(void* const* d_in, const int* in_sizes, int n_in,
                              void* d_out, int out_size) {
    const float* x     = (const float*)d_in[0];
    const int*   ei    = (const int*)d_in[1];   // [2, E] int32
    const int*   batch = (const int*)d_in[2];

    const float* Wl[3] = {(const float*)d_in[3],  (const float*)d_in[9],  (const float*)d_in[15]};
    const float* bl[3] = {(const float*)d_in[4],  (const float*)d_in[10], (const float*)d_in[16]};
    const float* Wr[3] = {(const float*)d_in[5],  (const float*)d_in[11], (const float*)d_in[17]};
    const float* br[3] = {(const float*)d_in[6],  (const float*)d_in[12], (const float*)d_in[18]};
    const float* at[3] = {(const float*)d_in[7],  (const float*)d_in[13], (const float*)d_in[19]};
    const float* bb[3] = {(const float*)d_in[8],  (const float*)d_in[14], (const float*)d_in[20]};
    const float* linW  = (const float*)d_in[21];
    const float* linb  = (const float*)d_in[22];
    float* out = (float*)d_out;

    int E = in_sizes[1] / 2;
    int nb = (NNODES + 1023) / 1024;

    cudaFuncSetAttribute(k_gemm_mma, cudaFuncAttributeMaxDynamicSharedMemorySize, SMEM_GEMM);

    // CSR build (per replay; deterministic work)
    k_zero_all<<<(NNODES + 255) / 256, 256>>>();
    k_hist<<<(E + 255) / 256, 256>>>(ei, E);
    k_scan1<<<nb, 1024>>>();
    k_scan3<<<nb, 1024>>>();
    k_scatter<<<(E + 255) / 256, 256>>>(ei, E);

    // weight split prep (cheap)
    k_wprep<<<(384 * 512 + 255) / 256, 256>>>(Wl[1], Wr[1], Wl[2], Wr[2]);

    // layer 0
    k_lin0<<<(NNODES * 128 + 255) / 256, 256>>>(x, Wl[0], bl[0], Wr[0], br[0]);
    k_edge<<<NNODES, 64>>>(at[0], bb[0]);

    // layers 1, 2: tensor-core split-bf16 GEMM then fused edge pass
    dim3 gg((NNODES + 127) / 128, 4, 2);
    k_gemm_mma<<<gg, 256, SMEM_GEMM>>>(0, bl[1], br[1]);
    k_edge<<<NNODES, 64>>>(at[1], bb[1]);
    k_gemm_mma<<<gg, 256, SMEM_GEMM>>>(2, bl[2], br[2]);
    k_edge<<<NNODES, 64>>>(at[2], bb[2]);

    // pool + final linear
    k_pool_acc<<<(NNODES + 63) / 64, 128>>>(batch);
    k_final<<<NGRAPHS, CDIM>>>(linW, linb, out);
}